// round 15
// baseline (speedup 1.0000x reference)
#include <cuda_runtime.h>
#include <math.h>

static constexpr long O_FEAS   = 0;            // reused as y1rawB after mix
static constexpr long O_BMEAN  = 1572864;
static constexpr long O_GXN    = 1574400;      // 1024
static constexpr long O_OUTRES = 1575936;
static constexpr long O_FDT    = 2100224;
static constexpr long O_G      = 2231296;
static constexpr long O_YIS    = 2297088;
static constexpr long O_MM     = 2362624;
static constexpr long O_RALOUT = 6556928;
static constexpr long O_RALT   = 7081216;
static constexpr long O_SIGT   = 7605504;
static constexpr long O_GUSB   = 8129792;
static constexpr long O_CSAB   = 8654080;
static constexpr long O_Y1RAW  = 9178368;
static constexpr long O_Y1     = 9702656;
static constexpr long O_Y2RAW  = 10226944;
static constexpr long SCRATCH  = 10751232;

__device__ __align__(256) float g_scratch[SCRATCH];

__device__ __forceinline__ float blockSum256(float v, float* red) {
    int lane = threadIdx.x & 31, w = threadIdx.x >> 5;
    #pragma unroll
    for (int o = 16; o; o >>= 1) v += __shfl_down_sync(0xffffffffu, v, o);
    if (lane == 0) red[w] = v;
    __syncthreads();
    if (threadIdx.x == 0) {
        float s = 0.f;
        #pragma unroll
        for (int i = 0; i < 8; i++) s += red[i];
        red[8] = s;
    }
    __syncthreads();
    return red[8];
}
__device__ __forceinline__ float blockMax256(float v, float* red) {
    int lane = threadIdx.x & 31, w = threadIdx.x >> 5;
    #pragma unroll
    for (int o = 16; o; o >>= 1) v = fmaxf(v, __shfl_down_sync(0xffffffffu, v, o));
    if (lane == 0) red[w] = v;
    __syncthreads();
    if (threadIdx.x == 0) {
        float s = red[0];
        #pragma unroll
        for (int i = 1; i < 8; i++) s = fmaxf(s, red[i]);
        red[8] = s;
    }
    __syncthreads();
    return red[8];
}

__device__ __forceinline__ unsigned cvt_tf32(float x) {
    unsigned r;
    asm("cvt.rna.tf32.f32 %0, %1;" : "=r"(r) : "f"(x));
    return r;
}
__device__ __forceinline__ void mma_tf32(float c[4], const unsigned a[4],
                                         const unsigned b[2]) {
    asm volatile(
        "mma.sync.aligned.m16n8k8.row.col.f32.tf32.tf32.f32 "
        "{%0,%1,%2,%3},{%4,%5,%6,%7},{%8,%9},{%0,%1,%2,%3};"
        : "+f"(c[0]), "+f"(c[1]), "+f"(c[2]), "+f"(c[3])
        : "r"(a[0]), "r"(a[1]), "r"(a[2]), "r"(a[3]), "r"(b[0]), "r"(b[1]));
}

// ---------------------------------------------------------------------------
// 1) Grouped conv as implicit GEMM on tensor cores (3xTF32).
//    Per block: one group (M=16 oc, one m16 tile) x 256 pixels.
//    B[k][n] = xt[koff[k] + noff[n]] read straight from the padded smem tile
//    (no im2col materialization). Weights pre-split hi/lo in smem.
//    Grid (4 quarters, 32 groups), 256 threads. Raw conv out (inorm separate).
// ---------------------------------------------------------------------------
template <int KW>
__global__ __launch_bounds__(256) void k_skmma(
    const float* __restrict__ x, const float* __restrict__ w,
    float* __restrict__ fea)
{
    constexpr int PAD  = (KW - 1) / 2;
    constexpr int S    = 32 + 2 * PAD;
    constexpr int SP   = (S + 3) & ~3;
    constexpr int TAPS = KW * KW;
    constexpr int K    = 16 * TAPS;           // 144 / 400 / 784, all %8==0
    extern __shared__ char smraw[];
    uint2* wsm  = (uint2*)smraw;                              // [K][16] hi/lo
    float* xt   = (float*)(smraw + (long)K * 16 * 8);         // [16][S*SP]
    int*   koff = (int*)(smraw + (long)K * 16 * 8 + 16 * S * SP * 4);

    const int q    = blockIdx.x;              // pixel quarter 0..3
    const int g    = blockIdx.y;              // group 0..31
    const int t    = threadIdx.x;
    const int lane = t & 31, wid = t >> 5;
    const int r    = lane >> 2, cl = lane & 3;
    const int n0   = q * 256 + wid * 32;

    // stage weights hi/lo: wsm[k][oc] from w[(g*16+oc)*K + k]
    for (int i = t; i < K * 16; i += 256) {
        int k = i >> 4, oc = i & 15;
        float v = w[(long)(g * 16 + oc) * K + k];
        unsigned h = cvt_tf32(v);
        wsm[k * 16 + oc] = make_uint2(h, cvt_tf32(v - __uint_as_float(h)));
    }
    // tap offset table: k = ci*TAPS + ky*KW + kx
    for (int k = t; k < K; k += 256) {
        int ci = k / TAPS, rem = k % TAPS;
        koff[k] = ci * S * SP + (rem / KW) * SP + (rem % KW);
    }
    // zero tiles, then fill interiors (padding ring stays zero)
    for (int i = t; i < 16 * S * SP; i += 256) xt[i] = 0.f;
    __syncthreads();
    const float* xg = x + (long)g * 16 * 1024;
    for (int i = t; i < 16 * 1024; i += 256) {
        int ci = i >> 10, p = i & 1023;
        xt[ci * S * SP + ((p >> 5) + PAD) * SP + (p & 31) + PAD] = xg[i];
    }
    __syncthreads();

    int noff[4];
    #pragma unroll
    for (int nt = 0; nt < 4; nt++) {
        int n = n0 + nt * 8 + r;
        noff[nt] = (n >> 5) * SP + (n & 31);
    }

    float acc[4][4] = {};
    for (int ks = 0; ks < K; ks += 8) {
        uint2 qa0 = wsm[(ks + cl) * 16 + r];
        uint2 qa1 = wsm[(ks + cl) * 16 + r + 8];
        uint2 qa2 = wsm[(ks + cl + 4) * 16 + r];
        uint2 qa3 = wsm[(ks + cl + 4) * 16 + r + 8];
        unsigned ah[4] = {qa0.x, qa1.x, qa2.x, qa3.x};
        unsigned al[4] = {qa0.y, qa1.y, qa2.y, qa3.y};
        int ko0 = koff[ks + cl], ko1 = koff[ks + cl + 4];
        #pragma unroll
        for (int nt = 0; nt < 4; nt++) {
            float v0 = xt[ko0 + noff[nt]];
            float v1 = xt[ko1 + noff[nt]];
            unsigned h0 = cvt_tf32(v0), h1 = cvt_tf32(v1);
            unsigned bh[2] = {h0, h1};
            unsigned bl[2] = {cvt_tf32(v0 - __uint_as_float(h0)),
                              cvt_tf32(v1 - __uint_as_float(h1))};
            mma_tf32(acc[nt], ah, bl);
            mma_tf32(acc[nt], al, bh);
            mma_tf32(acc[nt], ah, bh);
        }
    }
    #pragma unroll
    for (int nt = 0; nt < 4; nt++) {
        long row = (long)(g * 16 + r);
        int col = n0 + nt * 8 + cl * 2;
        *(float2*)(fea + row * 1024 + col) =
            make_float2(acc[nt][0], acc[nt][1]);
        *(float2*)(fea + (row + 8) * 1024 + col) =
            make_float2(acc[nt][2], acc[nt][3]);
    }
}

// 1b) instance norm + relu + channel mean, in place. grid 1536.
__global__ __launch_bounds__(256) void k_inrm(float* __restrict__ feas,
                                              float* __restrict__ bmean)
{
    __shared__ float red[9];
    int b = blockIdx.x, t = threadIdx.x;
    float* p = feas + (long)b * 1024;
    float v[4];
    #pragma unroll
    for (int qq = 0; qq < 4; qq++) v[qq] = p[t + qq * 256];
    float s  = v[0] + v[1] + v[2] + v[3];
    float sq = v[0]*v[0] + v[1]*v[1] + v[2]*v[2] + v[3]*v[3];
    s  = blockSum256(s,  red);
    sq = blockSum256(sq, red);
    float mean = s * (1.f / 1024.f);
    float var  = sq * (1.f / 1024.f) - mean * mean;
    float rstd = rsqrtf(var + 1e-5f);
    float rsum = 0.f;
    #pragma unroll
    for (int qq = 0; qq < 4; qq++) {
        float z = fmaxf((v[qq] - mean) * rstd, 0.f);
        p[t + qq * 256] = z;
        rsum += z;
    }
    rsum = blockSum256(rsum, red);
    if (t == 0) bmean[b] = rsum * (1.f / 1024.f);
}

// 2+3) fused: fea_z FC + attention softmax + mix + downsample-transpose.
__global__ __launch_bounds__(256) void k_mix_att_fcz(
    const float* __restrict__ feas, const float* __restrict__ bmean,
    const float* __restrict__ fc_w, const float* __restrict__ fc_b,
    const float* __restrict__ fcs_w, const float* __restrict__ fcs_b,
    float* __restrict__ outres, float* __restrict__ fdT)
{
    __shared__ float ssum[512];
    __shared__ float sz[32];
    int t = threadIdx.x, c = blockIdx.x;
    int lane = t & 31, w = t >> 5;
    for (int i = t; i < 512; i += 256)
        ssum[i] = bmean[i] + bmean[512 + i] + bmean[1024 + i];
    __syncthreads();
    #pragma unroll
    for (int dd = 0; dd < 4; dd++) {
        int d = w * 4 + dd;
        float a = 0.f;
        const float* fw = fc_w + d * 512;
        for (int ch = lane; ch < 512; ch += 32) a += ssum[ch] * fw[ch];
        #pragma unroll
        for (int o = 16; o; o >>= 1) a += __shfl_down_sync(0xffffffffu, a, o);
        if (lane == 0) sz[d] = a + fc_b[d];
    }
    __syncthreads();
    float av[3];
    #pragma unroll
    for (int m = 0; m < 3; m++) {
        float a = fcs_b[m * 512 + c];
        const float* fw = fcs_w + (m * 512 + c) * 32;
        #pragma unroll
        for (int d = 0; d < 32; d++) a += sz[d] * fw[d];
        av[m] = a;
    }
    float mx = fmaxf(av[0], fmaxf(av[1], av[2]));
    float e0 = expf(av[0] - mx), e1 = expf(av[1] - mx), e2 = expf(av[2] - mx);
    float inv = 1.f / (e0 + e1 + e2);
    #pragma unroll
    for (int qq = 0; qq < 4; qq++) {
        int o = t + qq * 256;
        long idx = (long)c * 1024 + o;
        float v = (e0 * feas[idx] + e1 * feas[524288 + idx]
                 + e2 * feas[1048576 + idx]) * inv;
        outres[idx] = v;
        int oy = o >> 5, ox = o & 31;
        if (!(oy & 1) && !(ox & 1))
            fdT[((oy >> 1) * 16 + (ox >> 1)) * 512 + c] = v;
    }
}

// gram (fp32, feeds exp): 256x256, K=512, 32x32 tiles
__global__ __launch_bounds__(256) void k_gram(const float* __restrict__ A,
                                              float* __restrict__ C)
{
    __shared__ float As[16][36];
    __shared__ float Bs[16][36];
    int tid = threadIdx.x;
    int m0 = blockIdx.y * 32, n0 = blockIdx.x * 32;
    int tx = tid & 15, ty = tid >> 4;
    int lm = (tid & 127) >> 2, lk4 = (tid & 3) * 4;
    float acc[2][2] = {};
    for (int kt = 0; kt < 512; kt += 16) {
        if (tid < 128) {
            float4 v = *(const float4*)(A + (long)(m0 + lm) * 512 + kt + lk4);
            As[lk4 + 0][lm] = v.x; As[lk4 + 1][lm] = v.y;
            As[lk4 + 2][lm] = v.z; As[lk4 + 3][lm] = v.w;
        } else {
            float4 v = *(const float4*)(A + (long)(n0 + lm) * 512 + kt + lk4);
            Bs[lk4 + 0][lm] = v.x; Bs[lk4 + 1][lm] = v.y;
            Bs[lk4 + 2][lm] = v.z; Bs[lk4 + 3][lm] = v.w;
        }
        __syncthreads();
        #pragma unroll
        for (int kk = 0; kk < 16; kk++) {
            float a0 = As[kk][ty * 2], a1 = As[kk][ty * 2 + 1];
            float b0 = Bs[kk][tx * 2], b1 = Bs[kk][tx * 2 + 1];
            acc[0][0] += a0 * b0; acc[0][1] += a0 * b1;
            acc[1][0] += a1 * b0; acc[1][1] += a1 * b1;
        }
        __syncthreads();
    }
    int m = m0 + ty * 2, n = n0 + tx * 2;
    C[m * 256 + n] = acc[0][0];       C[m * 256 + n + 1] = acc[0][1];
    C[(m + 1) * 256 + n] = acc[1][0]; C[(m + 1) * 256 + n + 1] = acc[1][1];
}

// ---------------------------------------------------------------------------
// 3xTF32 GEMM: uint2-packed hi/lo smem, term-major mmas.
// ---------------------------------------------------------------------------
__global__ __launch_bounds__(256) void gemm3_ab(
    const float* __restrict__ A, int lda,
    const float* __restrict__ B1, const float* __restrict__ B2, int K1,
    float* __restrict__ C, const float* __restrict__ Cacc,
    int M, int N, int K, float* __restrict__ CT, float* __restrict__ SigT)
{
    __shared__ __align__(16) char smraw[2 * 16 * 70 * 8];
    uint2 (*As)[70] = (uint2(*)[70])smraw;
    uint2 (*Bs)[70] = (uint2(*)[70])(smraw + 16 * 70 * 8);
    int tid = threadIdx.x;
    int lane = tid & 31, wid = tid >> 5;
    int wm = (wid >> 2) * 32, wn = (wid & 3) * 16;
    int m0 = blockIdx.y * 64, n0 = blockIdx.x * 64;
    int a_m = tid >> 2, a_k4 = (tid & 3) * 4;
    int b_k = tid >> 4, b_n4 = (tid & 15) * 4;
    int r = lane >> 2, cl = lane & 3;
    float cacc[2][2][4] = {};

    const float* aptr = A + (long)(m0 + a_m) * lda + a_k4;
    float4 av = *(const float4*)(aptr);
    const float* bs0 = (b_k < K1) ? (B1 + (long)b_k * N) : (B2 + (long)(b_k - K1) * N);
    float4 bv = *(const float4*)(bs0 + n0 + b_n4);

    for (int kt = 0; kt < K; kt += 16) {
        float va[4] = {av.x, av.y, av.z, av.w};
        float vb[4] = {bv.x, bv.y, bv.z, bv.w};
        #pragma unroll
        for (int i = 0; i < 4; i++) {
            unsigned h = cvt_tf32(va[i]);
            As[a_k4 + i][a_m] = make_uint2(h, cvt_tf32(va[i] - __uint_as_float(h)));
            unsigned g = cvt_tf32(vb[i]);
            Bs[b_k][b_n4 + i] = make_uint2(g, cvt_tf32(vb[i] - __uint_as_float(g)));
        }
        __syncthreads();
        if (kt + 16 < K) {
            av = *(const float4*)(aptr + kt + 16);
            int gk = kt + 16 + b_k;
            const float* src = (gk < K1) ? (B1 + (long)gk * N) : (B2 + (long)(gk - K1) * N);
            bv = *(const float4*)(src + n0 + b_n4);
        }
        #pragma unroll
        for (int ks = 0; ks < 16; ks += 8) {
            unsigned ah[2][4], al[2][4], bh[2][2], bl[2][2];
            #pragma unroll
            for (int mt = 0; mt < 2; mt++) {
                int mb = wm + mt * 16 + r;
                uint2 q0 = As[ks + cl][mb];
                uint2 q1 = As[ks + cl][mb + 8];
                uint2 q2 = As[ks + cl + 4][mb];
                uint2 q3 = As[ks + cl + 4][mb + 8];
                ah[mt][0] = q0.x; ah[mt][1] = q1.x; ah[mt][2] = q2.x; ah[mt][3] = q3.x;
                al[mt][0] = q0.y; al[mt][1] = q1.y; al[mt][2] = q2.y; al[mt][3] = q3.y;
            }
            #pragma unroll
            for (int nt = 0; nt < 2; nt++) {
                int nb = wn + nt * 8 + r;
                uint2 u0 = Bs[ks + cl][nb];
                uint2 u1 = Bs[ks + cl + 4][nb];
                bh[nt][0] = u0.x; bh[nt][1] = u1.x;
                bl[nt][0] = u0.y; bl[nt][1] = u1.y;
            }
            #pragma unroll
            for (int mt = 0; mt < 2; mt++)
                #pragma unroll
                for (int nt = 0; nt < 2; nt++) mma_tf32(cacc[mt][nt], ah[mt], bl[nt]);
            #pragma unroll
            for (int mt = 0; mt < 2; mt++)
                #pragma unroll
                for (int nt = 0; nt < 2; nt++) mma_tf32(cacc[mt][nt], al[mt], bh[nt]);
            #pragma unroll
            for (int mt = 0; mt < 2; mt++)
                #pragma unroll
                for (int nt = 0; nt < 2; nt++) mma_tf32(cacc[mt][nt], ah[mt], bh[nt]);
        }
        __syncthreads();
    }
    if (CT == nullptr) {
        #pragma unroll
        for (int mt = 0; mt < 2; mt++)
            #pragma unroll
            for (int nt = 0; nt < 2; nt++) {
                long row = m0 + wm + mt * 16 + r;
                long col = n0 + wn + nt * 8 + cl * 2;
                float2 o0 = make_float2(cacc[mt][nt][0], cacc[mt][nt][1]);
                float2 o1 = make_float2(cacc[mt][nt][2], cacc[mt][nt][3]);
                if (Cacc) {
                    float2 p0 = *(const float2*)(Cacc + row * N + col);
                    float2 p1 = *(const float2*)(Cacc + (row + 8) * N + col);
                    o0.x += p0.x; o0.y += p0.y;
                    o1.x += p1.x; o1.y += p1.y;
                }
                *(float2*)(C + row * N + col) = o0;
                *(float2*)(C + (row + 8) * N + col) = o1;
            }
    } else {
        float* T = (float*)smraw;  // 64x67 = 17152 B <= 17920
        #pragma unroll
        for (int mt = 0; mt < 2; mt++)
            #pragma unroll
            for (int nt = 0; nt < 2; nt++) {
                int row = wm + mt * 16 + r;
                int col = wn + nt * 8 + cl * 2;
                T[row * 67 + col]           = cacc[mt][nt][0];
                T[row * 67 + col + 1]       = cacc[mt][nt][1];
                T[(row + 8) * 67 + col]     = cacc[mt][nt][2];
                T[(row + 8) * 67 + col + 1] = cacc[mt][nt][3];
            }
        __syncthreads();
        for (int i = tid; i < 4096; i += 256) {
            int ml = i >> 6, nl = i & 63;
            C[(long)(m0 + ml) * N + n0 + nl] = T[ml * 67 + nl];
        }
        for (int i = tid; i < 4096; i += 256) {
            int nl = i >> 6, ml = i & 63;
            float v = T[ml * 67 + nl];
            long off = (long)(n0 + nl) * M + m0 + ml;
            CT[off] = v;
            SigT[off] = 1.f / (1.f + expf(-v));
        }
    }
}

// yi from gram + column softmax
__global__ __launch_bounds__(256) void k_yis(const float* __restrict__ G,
                                             float* __restrict__ yis)
{
    __shared__ float red[9];
    int s = blockIdx.x, p = threadIdx.x;
    int sy = s >> 4, sx = s & 15;
    int py = p >> 4, px = p & 15;
    float raw = 0.f, nsum = 0.f;
    #pragma unroll
    for (int dy = -1; dy <= 1; dy++)
        #pragma unroll
        for (int dx = -1; dx <= 1; dx++) {
            int qy = py + dy, qx = px + dx;
            if (qy >= 0 && qy < 16 && qx >= 0 && qx < 16) {
                int q = qy * 16 + qx;
                nsum += G[q * 256 + q];
                int ry = sy + dy, rx = sx + dx;
                if (ry >= 0 && ry < 16 && rx >= 0 && rx < 16)
                    raw += G[q * 256 + ry * 16 + rx];
            }
        }
    float nrm = fmaxf(sqrtf(nsum), 1e-4f);
    float v = 10.f * raw / nrm;
    float mx = blockMax256(v, red);
    float e = expf(v - mx);
    float ssum = blockSum256(e, red);
    yis[p * 256 + s] = e / ssum;
}

// combined deconv matrix M[q][o]
__global__ __launch_bounds__(256) void k_buildM(const float* __restrict__ yis,
                                                float* __restrict__ Mm)
{
    int idx = blockIdx.x * 256 + threadIdx.x;
    int o = idx & 1023, q = idx >> 10;
    int oy = o >> 5, ox = o & 31;
    int qrow = q >> 5, qcol = q & 31;
    int kyv[2], syv[2], kxv[2], sxv[2];
    if (oy & 1) { kyv[0] = 1; syv[0] = (oy - 1) >> 1; kyv[1] = 3; syv[1] = (oy + 1) >> 1; }
    else        { kyv[0] = 0; syv[0] = (oy >> 1) - 1; kyv[1] = 2; syv[1] = oy >> 1; }
    if (ox & 1) { kxv[0] = 1; sxv[0] = (ox - 1) >> 1; kxv[1] = 3; sxv[1] = (ox + 1) >> 1; }
    else        { kxv[0] = 0; sxv[0] = (ox >> 1) - 1; kxv[1] = 2; sxv[1] = ox >> 1; }
    float acc = 0.f;
    #pragma unroll
    for (int a = 0; a < 2; a++) {
        if (syv[a] < 0 || syv[a] > 15) continue;
        int ty = qrow - 2 + kyv[a];
        if (ty < 0 || ty >= 32 || (ty & 1)) continue;
        int py = ty >> 1;
        #pragma unroll
        for (int b = 0; b < 2; b++) {
            if (sxv[b] < 0 || sxv[b] > 15) continue;
            int tx = qcol - 2 + kxv[b];
            if (tx < 0 || tx >= 32 || (tx & 1)) continue;
            acc += yis[(py * 16 + (tx >> 1)) * 256 + syv[a] * 16 + sxv[b]];
        }
    }
    Mm[idx] = 0.25f * acc;
}

// extract 1D gaussian rows
__global__ void k_gxn(const float* __restrict__ gus, float* __restrict__ gxn)
{
    int t = threadIdx.x;
    int i = t >> 5, h = t & 31;
    const float* row = gus + (long)(i * 32) * 1024 + h * 32;
    float s = 0.f;
    #pragma unroll
    for (int w = 0; w < 32; w++) s += row[w];
    gxn[t] = s;
}

// exact separable gaussian blur
__global__ __launch_bounds__(256) void k_gus_blur(
    const float* __restrict__ ralout, const float* __restrict__ gxn,
    float* __restrict__ gusb)
{
    __shared__ float xsb[1024], gb[1024], t1[1024];
    int c = blockIdx.x, t = threadIdx.x;
    for (int i = t; i < 1024; i += 256) {
        xsb[i] = ralout[c * 1024 + i];
        gb[i]  = gxn[i];
    }
    __syncthreads();
    for (int i = t; i < 1024; i += 256) {
        int py = i >> 5, w = i & 31;
        float s = 0.f;
        #pragma unroll
        for (int h = 0; h < 32; h++) s += gb[py * 32 + h] * xsb[h * 32 + w];
        t1[i] = s;
    }
    __syncthreads();
    for (int i = t; i < 1024; i += 256) {
        int py = i >> 5, px = i & 31;
        float s = 0.f;
        #pragma unroll
        for (int w = 0; w < 32; w++) s += gb[px * 32 + w] * t1[py * 32 + w];
        gusb[(long)i * 512 + c] = s;
    }
}

// csa
__global__ __launch_bounds__(256) void k_csa(const float* __restrict__ sigT,
                                             const float* __restrict__ ralT,
                                             float* __restrict__ csab)
{
    __shared__ float ws[8][9];
    __shared__ float a9[9];
    int p = blockIdx.x, t = threadIdx.x;
    int lane = t & 31, w = t >> 5;
    int py = p >> 5, px = p & 31;
    int nb[9]; bool ok[9];
    #pragma unroll
    for (int d = 0; d < 9; d++) {
        int dy = d / 3 - 1, dx = d % 3 - 1;
        int y = py + dy, x = px + dx;
        ok[d] = (y >= 0 && y < 32 && x >= 0 && x < 32);
        nb[d] = ok[d] ? (y * 32 + x) : 0;
    }
    float loc[9] = {};
    for (int c = t; c < 512; c += 256) {
        float sv = sigT[p * 512 + c];
        #pragma unroll
        for (int d = 0; d < 9; d++)
            if (ok[d]) loc[d] += sv * sigT[nb[d] * 512 + c];
    }
    #pragma unroll
    for (int d = 0; d < 9; d++) {
        #pragma unroll
        for (int o = 16; o; o >>= 1) loc[d] += __shfl_down_sync(0xffffffffu, loc[d], o);
        if (lane == 0) ws[w][d] = loc[d];
    }
    __syncthreads();
    if (t < 9) {
        float s = 0.f;
        #pragma unroll
        for (int i = 0; i < 8; i++) s += ws[i][t];
        a9[t] = s * (1.f / 512.f);
    }
    __syncthreads();
    float mx = -1e30f;
    #pragma unroll
    for (int d = 0; d < 9; d++) mx = fmaxf(mx, a9[d]);
    float wgt[9]; float ssum = 0.f;
    #pragma unroll
    for (int d = 0; d < 9; d++) { wgt[d] = expf(a9[d] - mx); ssum += wgt[d]; }
    float inv = 1.f / ssum;
    for (int c = t; c < 512; c += 256) {
        float acc = 0.f;
        #pragma unroll
        for (int d = 0; d < 9; d++)
            if (ok[d]) acc += wgt[d] * ralT[nb[d] * 512 + c];
        csab[p * 512 + c] = acc * inv;
    }
}

// instance norm + leaky relu 0.2 (single input)
__global__ __launch_bounds__(256) void k_inorm_lrelu(const float* __restrict__ in,
                                                     float* __restrict__ out)
{
    __shared__ float red[9];
    int c = blockIdx.x, t = threadIdx.x;
    float v[4];
    #pragma unroll
    for (int q = 0; q < 4; q++) v[q] = in[c * 1024 + t + q * 256];
    float s  = v[0] + v[1] + v[2] + v[3];
    float sq = v[0]*v[0] + v[1]*v[1] + v[2]*v[2] + v[3]*v[3];
    s  = blockSum256(s,  red);
    sq = blockSum256(sq, red);
    float mean = s * (1.f / 1024.f);
    float var  = sq * (1.f / 1024.f) - mean * mean;
    float rstd = rsqrtf(var + 1e-5f);
    #pragma unroll
    for (int q = 0; q < 4; q++) {
        float z = (v[q] - mean) * rstd;
        out[c * 1024 + t + q * 256] = (z >= 0.f) ? z : 0.2f * z;
    }
}

// add two partials + instance norm + leaky relu 0.2
__global__ __launch_bounds__(256) void k_add_inorm_lrelu(
    const float* __restrict__ inA, const float* __restrict__ inB,
    float* __restrict__ out)
{
    __shared__ float red[9];
    int c = blockIdx.x, t = threadIdx.x;
    float v[4];
    #pragma unroll
    for (int q = 0; q < 4; q++) {
        long i = (long)c * 1024 + t + q * 256;
        v[q] = inA[i] + inB[i];
    }
    float s  = v[0] + v[1] + v[2] + v[3];
    float sq = v[0]*v[0] + v[1]*v[1] + v[2]*v[2] + v[3]*v[3];
    s  = blockSum256(s,  red);
    sq = blockSum256(sq, red);
    float mean = s * (1.f / 1024.f);
    float var  = sq * (1.f / 1024.f) - mean * mean;
    float rstd = rsqrtf(var + 1e-5f);
    #pragma unroll
    for (int q = 0; q < 4; q++) {
        float z = (v[q] - mean) * rstd;
        out[c * 1024 + t + q * 256] = (z >= 0.f) ? z : 0.2f * z;
    }
}

// ---------------------------------------------------------------------------
extern "C" void kernel_launch(void* const* d_in, const int* in_sizes, int n_in,
                              void* d_out, int out_size)
{
    const float* x      = (const float*)d_in[0];
    const float* gus    = (const float*)d_in[1];
    const float* w3     = (const float*)d_in[2];
    const float* w5     = (const float*)d_in[4];
    const float* w7     = (const float*)d_in[6];
    const float* fc_w   = (const float*)d_in[8];
    const float* fc_b   = (const float*)d_in[9];
    const float* fcs_w  = (const float*)d_in[10];
    const float* fcs_b  = (const float*)d_in[11];
    const float* down_w = (const float*)d_in[12];
    const float* fuse_w = (const float*)d_in[13];
    float* out = (float*)d_out;

    void* sp = nullptr;
    cudaGetSymbolAddress(&sp, g_scratch);
    float* S = (float*)sp;
    float* feas   = S + O_FEAS;
    float* y1rawB = S + O_FEAS;          // reuse: feas dead after mix
    float* bmean  = S + O_BMEAN;
    float* gxn    = S + O_GXN;
    float* outres = S + O_OUTRES;
    float* fdT    = S + O_FDT;
    float* G      = S + O_G;
    float* yis    = S + O_YIS;
    float* Mm     = S + O_MM;
    float* ralout = S + O_RALOUT;
    float* ralT   = S + O_RALT;
    float* sigT   = S + O_SIGT;
    float* gusb   = S + O_GUSB;
    float* csab   = S + O_CSAB;
    float* y1raw  = S + O_Y1RAW;
    float* y1     = S + O_Y1;
    float* y2raw  = S + O_Y2RAW;

    // smem: weights hi/lo (K*16*8) + tile (16*S*SP*4) + koff (K*4)
    constexpr int SM3 = 144 * 16 * 8 + 16 * 34 * 36 * 4 + 144 * 4;  //  97344
    constexpr int SM5 = 400 * 16 * 8 + 16 * 36 * 36 * 4 + 400 * 4;  // 135744
    constexpr int SM7 = 784 * 16 * 8 + 16 * 38 * 40 * 4 + 784 * 4;  // 200768

    static cudaStream_t s1 = nullptr, s2 = nullptr;
    static cudaEvent_t evA, ev1, ev2, evM, ev5, evC, ev4;
    if (!s1) {
        cudaStreamCreateWithFlags(&s1, cudaStreamNonBlocking);
        cudaStreamCreateWithFlags(&s2, cudaStreamNonBlocking);
        cudaEventCreateWithFlags(&evA, cudaEventDisableTiming);
        cudaEventCreateWithFlags(&ev1, cudaEventDisableTiming);
        cudaEventCreateWithFlags(&ev2, cudaEventDisableTiming);
        cudaEventCreateWithFlags(&evM, cudaEventDisableTiming);
        cudaEventCreateWithFlags(&ev5, cudaEventDisableTiming);
        cudaEventCreateWithFlags(&evC, cudaEventDisableTiming);
        cudaEventCreateWithFlags(&ev4, cudaEventDisableTiming);
        cudaFuncSetAttribute(k_skmma<3>,
            cudaFuncAttributeMaxDynamicSharedMemorySize, SM3);
        cudaFuncSetAttribute(k_skmma<5>,
            cudaFuncAttributeMaxDynamicSharedMemorySize, SM5);
        cudaFuncSetAttribute(k_skmma<7>,
            cudaFuncAttributeMaxDynamicSharedMemorySize, SM7);
    }

    // fork: 3 tensor-core conv kernels + gxn extraction concurrent
    cudaEventRecord(evA, 0);
    cudaStreamWaitEvent(s1, evA, 0);
    cudaStreamWaitEvent(s2, evA, 0);
    k_gxn<<<1, 1024, 0, s2>>>(gus, gxn);
    k_skmma<3><<<dim3(4, 32), 256, SM3, 0 >>>(x, w3, feas);
    k_skmma<5><<<dim3(4, 32), 256, SM5, s1>>>(x, w5, feas + 524288);
    k_skmma<7><<<dim3(4, 32), 256, SM7, s2>>>(x, w7, feas + 1048576);
    cudaEventRecord(ev1, s1);
    cudaEventRecord(ev2, s2);
    cudaStreamWaitEvent(0, ev1, 0);
    cudaStreamWaitEvent(0, ev2, 0);

    k_inrm<<<1536, 256>>>(feas, bmean);
    k_mix_att_fcz<<<512, 256>>>(feas, bmean, fc_w, fc_b, fcs_w, fcs_b,
                                outres, fdT);

    // early fuse-partial on s2: y2raw = fuse_w[:,512:] * outres
    cudaEventRecord(evM, 0);
    cudaStreamWaitEvent(s2, evM, 0);
    gemm3_ab<<<dim3(16, 8, 1), 256, 0, s2>>>(fuse_w + 512, 1024,
                                             outres, outres, 512, y2raw, nullptr,
                                             512, 1024, 512, nullptr, nullptr);
    cudaEventRecord(ev5, s2);

    k_gram<<<dim3(8, 8), 256>>>(fdT, G);
    k_yis<<<256, 256>>>(G, yis);
    k_buildM<<<4096, 256>>>(yis, Mm);
    gemm3_ab<<<dim3(16, 8, 1), 256>>>(outres, 1024, Mm, Mm, 1024, ralout,
                                      nullptr, 512, 1024, 1024, ralT, sigT);

    // fork: csa -> downB on s1; blur -> downA on 0
    cudaEventRecord(evC, 0);
    cudaStreamWaitEvent(s1, evC, 0);
    k_csa<<<1024, 256, 0, s1>>>(sigT, ralT, csab);
    gemm3_ab<<<dim3(16, 8, 1), 256, 0, s1>>>(down_w + 512, 1024, csab, csab,
                                             512, y1rawB, nullptr,
                                             512, 1024, 512, nullptr, nullptr);
    cudaEventRecord(ev4, s1);
    k_gus_blur<<<512, 256>>>(ralout, gxn, gusb);
    gemm3_ab<<<dim3(16, 8, 1), 256>>>(down_w, 1024, gusb, gusb, 512, y1raw,
                                      nullptr, 512, 1024, 512, nullptr, nullptr);
    cudaStreamWaitEvent(0, ev4, 0);
    k_add_inorm_lrelu<<<512, 256>>>(y1raw, y1rawB, y1);

    // fuse-final: y2raw += fuse_w[:,:512] * y1
    cudaStreamWaitEvent(0, ev5, 0);
    gemm3_ab<<<dim3(16, 8, 1), 256>>>(fuse_w, 1024, y1, y1, 512, y2raw,
                                      y2raw, 512, 1024, 512, nullptr, nullptr);
    k_inorm_lrelu<<<512, 256>>>(y2raw, out);
}

// round 16
// speedup vs baseline: 1.1630x; 1.1630x over previous
#include <cuda_runtime.h>
#include <math.h>

static constexpr long O_FEAS   = 0;            // reused as y1rawB after mix
static constexpr long O_BMEAN  = 1572864;
static constexpr long O_GXN    = 1574400;      // 1024
static constexpr long O_OUTRES = 1575936;
static constexpr long O_FDT    = 2100224;
static constexpr long O_G      = 2231296;
static constexpr long O_YIS    = 2297088;
static constexpr long O_MM     = 2362624;
static constexpr long O_RALOUT = 6556928;
static constexpr long O_RALT   = 7081216;
static constexpr long O_SIGT   = 7605504;
static constexpr long O_GUSB   = 8129792;
static constexpr long O_CSAB   = 8654080;
static constexpr long O_Y1RAW  = 9178368;
static constexpr long O_Y1     = 9702656;
static constexpr long O_Y2RAW  = 10226944;
static constexpr long SCRATCH  = 10751232;

__device__ __align__(256) float g_scratch[SCRATCH];

__device__ __forceinline__ float blockSum256(float v, float* red) {
    int lane = threadIdx.x & 31, w = threadIdx.x >> 5;
    #pragma unroll
    for (int o = 16; o; o >>= 1) v += __shfl_down_sync(0xffffffffu, v, o);
    if (lane == 0) red[w] = v;
    __syncthreads();
    if (threadIdx.x == 0) {
        float s = 0.f;
        #pragma unroll
        for (int i = 0; i < 8; i++) s += red[i];
        red[8] = s;
    }
    __syncthreads();
    return red[8];
}
__device__ __forceinline__ float blockMax256(float v, float* red) {
    int lane = threadIdx.x & 31, w = threadIdx.x >> 5;
    #pragma unroll
    for (int o = 16; o; o >>= 1) v = fmaxf(v, __shfl_down_sync(0xffffffffu, v, o));
    if (lane == 0) red[w] = v;
    __syncthreads();
    if (threadIdx.x == 0) {
        float s = red[0];
        #pragma unroll
        for (int i = 1; i < 8; i++) s = fmaxf(s, red[i]);
        red[8] = s;
    }
    __syncthreads();
    return red[8];
}

__device__ __forceinline__ unsigned cvt_tf32(float x) {
    unsigned r;
    asm("cvt.rna.tf32.f32 %0, %1;" : "=r"(r) : "f"(x));
    return r;
}
__device__ __forceinline__ void mma_tf32(float c[4], const unsigned a[4],
                                         const unsigned b[2]) {
    asm volatile(
        "mma.sync.aligned.m16n8k8.row.col.f32.tf32.tf32.f32 "
        "{%0,%1,%2,%3},{%4,%5,%6,%7},{%8,%9},{%0,%1,%2,%3};"
        : "+f"(c[0]), "+f"(c[1]), "+f"(c[2]), "+f"(c[3])
        : "r"(a[0]), "r"(a[1]), "r"(a[2]), "r"(a[3]), "r"(b[0]), "r"(b[1]));
}

// ---------------------------------------------------------------------------
// 1) Grouped conv + inorm + relu + mean, OC4-blocked, all 16 input channels
//    resident, one barrier, padded row stride for vectorized window loads.
//    (Verified R14 form: k7 = 38.6us, near fp32 FMA-issue floor.)
// ---------------------------------------------------------------------------
template <int KW>
__global__ __launch_bounds__(256) void k_skconv(
    const float* __restrict__ x, const float* __restrict__ w,
    float* __restrict__ fea, float* __restrict__ bmean)
{
    constexpr int PAD  = (KW - 1) / 2;
    constexpr int S    = 32 + 2 * PAD;
    constexpr int SP   = (S + 3) & ~3;
    constexpr int TAPS = KW * KW;
    extern __shared__ float sm[];
    float* wsm = sm;
    float* xt  = sm + 16 * TAPS * 4;
    __shared__ float red[9];

    const int g   = blockIdx.x >> 2;
    const int oc0 = g * 16 + (blockIdx.x & 3) * 4;
    const int t   = threadIdx.x;
    const int py  = t >> 3;
    const int tx4 = (t & 7) * 4;

    for (int i = t; i < 16 * TAPS * 4; i += 256) {
        int l = i & 3, rest = i >> 2;
        wsm[i] = w[(long)(oc0 + l) * (16 * TAPS) + rest];
    }
    for (int i = t; i < 16 * S * SP; i += 256) xt[i] = 0.f;
    __syncthreads();
    const float* xg = x + (long)g * 16 * 1024;
    for (int i = t; i < 16 * 1024; i += 256) {
        int ci = i >> 10, p = i & 1023;
        int r = p >> 5, c = p & 31;
        xt[ci * S * SP + (r + PAD) * SP + (c + PAD)] = xg[i];
    }
    __syncthreads();

    float acc[4][4] = {};
    for (int ci = 0; ci < 16; ci++) {
        const float* base = xt + ci * S * SP;
        const float4* wq = (const float4*)wsm + ci * TAPS;
        #pragma unroll
        for (int ky = 0; ky < KW; ky++) {
            const float* xr = base + (py + ky) * SP + tx4;
            float xv[KW + 3];
            #pragma unroll
            for (int j4 = 0; j4 < (KW + 3) / 4; j4++) {
                float4 v = *(const float4*)(xr + j4 * 4);
                xv[j4 * 4 + 0] = v.x; xv[j4 * 4 + 1] = v.y;
                xv[j4 * 4 + 2] = v.z; xv[j4 * 4 + 3] = v.w;
            }
            if constexpr (((KW + 3) & 3) == 2) {
                float2 v = *(const float2*)(xr + ((KW + 3) & ~3));
                xv[(KW + 3) & ~3]       = v.x;
                xv[((KW + 3) & ~3) + 1] = v.y;
            }
            #pragma unroll
            for (int kx = 0; kx < KW; kx++) {
                float4 wv = wq[ky * KW + kx];
                acc[0][0] = fmaf(wv.x, xv[kx    ], acc[0][0]);
                acc[0][1] = fmaf(wv.x, xv[kx + 1], acc[0][1]);
                acc[0][2] = fmaf(wv.x, xv[kx + 2], acc[0][2]);
                acc[0][3] = fmaf(wv.x, xv[kx + 3], acc[0][3]);
                acc[1][0] = fmaf(wv.y, xv[kx    ], acc[1][0]);
                acc[1][1] = fmaf(wv.y, xv[kx + 1], acc[1][1]);
                acc[1][2] = fmaf(wv.y, xv[kx + 2], acc[1][2]);
                acc[1][3] = fmaf(wv.y, xv[kx + 3], acc[1][3]);
                acc[2][0] = fmaf(wv.z, xv[kx    ], acc[2][0]);
                acc[2][1] = fmaf(wv.z, xv[kx + 1], acc[2][1]);
                acc[2][2] = fmaf(wv.z, xv[kx + 2], acc[2][2]);
                acc[2][3] = fmaf(wv.z, xv[kx + 3], acc[2][3]);
                acc[3][0] = fmaf(wv.w, xv[kx    ], acc[3][0]);
                acc[3][1] = fmaf(wv.w, xv[kx + 1], acc[3][1]);
                acc[3][2] = fmaf(wv.w, xv[kx + 2], acc[3][2]);
                acc[3][3] = fmaf(wv.w, xv[kx + 3], acc[3][3]);
            }
        }
    }
    __syncthreads();
    #pragma unroll
    for (int l = 0; l < 4; l++) {
        float s  = acc[l][0] + acc[l][1] + acc[l][2] + acc[l][3];
        float sq = acc[l][0]*acc[l][0] + acc[l][1]*acc[l][1]
                 + acc[l][2]*acc[l][2] + acc[l][3]*acc[l][3];
        s  = blockSum256(s,  red);
        sq = blockSum256(sq, red);
        float mean = s * (1.f / 1024.f);
        float var  = sq * (1.f / 1024.f) - mean * mean;
        float rstd = rsqrtf(var + 1e-5f);
        float v0 = fmaxf((acc[l][0] - mean) * rstd, 0.f);
        float v1 = fmaxf((acc[l][1] - mean) * rstd, 0.f);
        float v2 = fmaxf((acc[l][2] - mean) * rstd, 0.f);
        float v3 = fmaxf((acc[l][3] - mean) * rstd, 0.f);
        *(float4*)(fea + (long)(oc0 + l) * 1024 + py * 32 + tx4) =
            make_float4(v0, v1, v2, v3);
        float rsum = blockSum256(v0 + v1 + v2 + v3, red);
        if (t == 0) bmean[oc0 + l] = rsum * (1.f / 1024.f);
    }
}

// 2+3) fused: fea_z FC + attention softmax + mix + downsample-transpose.
__global__ __launch_bounds__(256) void k_mix_att_fcz(
    const float* __restrict__ feas, const float* __restrict__ bmean,
    const float* __restrict__ fc_w, const float* __restrict__ fc_b,
    const float* __restrict__ fcs_w, const float* __restrict__ fcs_b,
    float* __restrict__ outres, float* __restrict__ fdT)
{
    __shared__ float ssum[512];
    __shared__ float sz[32];
    int t = threadIdx.x, c = blockIdx.x;
    int lane = t & 31, w = t >> 5;
    for (int i = t; i < 512; i += 256)
        ssum[i] = bmean[i] + bmean[512 + i] + bmean[1024 + i];
    __syncthreads();
    #pragma unroll
    for (int dd = 0; dd < 4; dd++) {
        int d = w * 4 + dd;
        float a = 0.f;
        const float* fw = fc_w + d * 512;
        for (int ch = lane; ch < 512; ch += 32) a += ssum[ch] * fw[ch];
        #pragma unroll
        for (int o = 16; o; o >>= 1) a += __shfl_down_sync(0xffffffffu, a, o);
        if (lane == 0) sz[d] = a + fc_b[d];
    }
    __syncthreads();
    float av[3];
    #pragma unroll
    for (int m = 0; m < 3; m++) {
        float a = fcs_b[m * 512 + c];
        const float* fw = fcs_w + (m * 512 + c) * 32;
        #pragma unroll
        for (int d = 0; d < 32; d++) a += sz[d] * fw[d];
        av[m] = a;
    }
    float mx = fmaxf(av[0], fmaxf(av[1], av[2]));
    float e0 = expf(av[0] - mx), e1 = expf(av[1] - mx), e2 = expf(av[2] - mx);
    float inv = 1.f / (e0 + e1 + e2);
    #pragma unroll
    for (int qq = 0; qq < 4; qq++) {
        int o = t + qq * 256;
        long idx = (long)c * 1024 + o;
        float v = (e0 * feas[idx] + e1 * feas[524288 + idx]
                 + e2 * feas[1048576 + idx]) * inv;
        outres[idx] = v;
        int oy = o >> 5, ox = o & 31;
        if (!(oy & 1) && !(ox & 1))
            fdT[((oy >> 1) * 16 + (ox >> 1)) * 512 + c] = v;
    }
}

// gram (fp32, feeds exp): 256x256, K=512, 32x32 tiles
__global__ __launch_bounds__(256) void k_gram(const float* __restrict__ A,
                                              float* __restrict__ C)
{
    __shared__ float As[16][36];
    __shared__ float Bs[16][36];
    int tid = threadIdx.x;
    int m0 = blockIdx.y * 32, n0 = blockIdx.x * 32;
    int tx = tid & 15, ty = tid >> 4;
    int lm = (tid & 127) >> 2, lk4 = (tid & 3) * 4;
    float acc[2][2] = {};
    for (int kt = 0; kt < 512; kt += 16) {
        if (tid < 128) {
            float4 v = *(const float4*)(A + (long)(m0 + lm) * 512 + kt + lk4);
            As[lk4 + 0][lm] = v.x; As[lk4 + 1][lm] = v.y;
            As[lk4 + 2][lm] = v.z; As[lk4 + 3][lm] = v.w;
        } else {
            float4 v = *(const float4*)(A + (long)(n0 + lm) * 512 + kt + lk4);
            Bs[lk4 + 0][lm] = v.x; Bs[lk4 + 1][lm] = v.y;
            Bs[lk4 + 2][lm] = v.z; Bs[lk4 + 3][lm] = v.w;
        }
        __syncthreads();
        #pragma unroll
        for (int kk = 0; kk < 16; kk++) {
            float a0 = As[kk][ty * 2], a1 = As[kk][ty * 2 + 1];
            float b0 = Bs[kk][tx * 2], b1 = Bs[kk][tx * 2 + 1];
            acc[0][0] += a0 * b0; acc[0][1] += a0 * b1;
            acc[1][0] += a1 * b0; acc[1][1] += a1 * b1;
        }
        __syncthreads();
    }
    int m = m0 + ty * 2, n = n0 + tx * 2;
    C[m * 256 + n] = acc[0][0];       C[m * 256 + n + 1] = acc[0][1];
    C[(m + 1) * 256 + n] = acc[1][0]; C[(m + 1) * 256 + n + 1] = acc[1][1];
}

// ---------------------------------------------------------------------------
// 3xTF32 GEMM: uint2-packed hi/lo smem, term-major mmas.
// ---------------------------------------------------------------------------
__global__ __launch_bounds__(256) void gemm3_ab(
    const float* __restrict__ A, int lda,
    const float* __restrict__ B1, const float* __restrict__ B2, int K1,
    float* __restrict__ C, const float* __restrict__ Cacc,
    int M, int N, int K, float* __restrict__ CT, float* __restrict__ SigT)
{
    __shared__ __align__(16) char smraw[2 * 16 * 70 * 8];
    uint2 (*As)[70] = (uint2(*)[70])smraw;
    uint2 (*Bs)[70] = (uint2(*)[70])(smraw + 16 * 70 * 8);
    int tid = threadIdx.x;
    int lane = tid & 31, wid = tid >> 5;
    int wm = (wid >> 2) * 32, wn = (wid & 3) * 16;
    int m0 = blockIdx.y * 64, n0 = blockIdx.x * 64;
    int a_m = tid >> 2, a_k4 = (tid & 3) * 4;
    int b_k = tid >> 4, b_n4 = (tid & 15) * 4;
    int r = lane >> 2, cl = lane & 3;
    float cacc[2][2][4] = {};

    const float* aptr = A + (long)(m0 + a_m) * lda + a_k4;
    float4 av = *(const float4*)(aptr);
    const float* bs0 = (b_k < K1) ? (B1 + (long)b_k * N) : (B2 + (long)(b_k - K1) * N);
    float4 bv = *(const float4*)(bs0 + n0 + b_n4);

    for (int kt = 0; kt < K; kt += 16) {
        float va[4] = {av.x, av.y, av.z, av.w};
        float vb[4] = {bv.x, bv.y, bv.z, bv.w};
        #pragma unroll
        for (int i = 0; i < 4; i++) {
            unsigned h = cvt_tf32(va[i]);
            As[a_k4 + i][a_m] = make_uint2(h, cvt_tf32(va[i] - __uint_as_float(h)));
            unsigned g = cvt_tf32(vb[i]);
            Bs[b_k][b_n4 + i] = make_uint2(g, cvt_tf32(vb[i] - __uint_as_float(g)));
        }
        __syncthreads();
        if (kt + 16 < K) {
            av = *(const float4*)(aptr + kt + 16);
            int gk = kt + 16 + b_k;
            const float* src = (gk < K1) ? (B1 + (long)gk * N) : (B2 + (long)(gk - K1) * N);
            bv = *(const float4*)(src + n0 + b_n4);
        }
        #pragma unroll
        for (int ks = 0; ks < 16; ks += 8) {
            unsigned ah[2][4], al[2][4], bh[2][2], bl[2][2];
            #pragma unroll
            for (int mt = 0; mt < 2; mt++) {
                int mb = wm + mt * 16 + r;
                uint2 q0 = As[ks + cl][mb];
                uint2 q1 = As[ks + cl][mb + 8];
                uint2 q2 = As[ks + cl + 4][mb];
                uint2 q3 = As[ks + cl + 4][mb + 8];
                ah[mt][0] = q0.x; ah[mt][1] = q1.x; ah[mt][2] = q2.x; ah[mt][3] = q3.x;
                al[mt][0] = q0.y; al[mt][1] = q1.y; al[mt][2] = q2.y; al[mt][3] = q3.y;
            }
            #pragma unroll
            for (int nt = 0; nt < 2; nt++) {
                int nb = wn + nt * 8 + r;
                uint2 u0 = Bs[ks + cl][nb];
                uint2 u1 = Bs[ks + cl + 4][nb];
                bh[nt][0] = u0.x; bh[nt][1] = u1.x;
                bl[nt][0] = u0.y; bl[nt][1] = u1.y;
            }
            #pragma unroll
            for (int mt = 0; mt < 2; mt++)
                #pragma unroll
                for (int nt = 0; nt < 2; nt++) mma_tf32(cacc[mt][nt], ah[mt], bl[nt]);
            #pragma unroll
            for (int mt = 0; mt < 2; mt++)
                #pragma unroll
                for (int nt = 0; nt < 2; nt++) mma_tf32(cacc[mt][nt], al[mt], bh[nt]);
            #pragma unroll
            for (int mt = 0; mt < 2; mt++)
                #pragma unroll
                for (int nt = 0; nt < 2; nt++) mma_tf32(cacc[mt][nt], ah[mt], bh[nt]);
        }
        __syncthreads();
    }
    if (CT == nullptr) {
        #pragma unroll
        for (int mt = 0; mt < 2; mt++)
            #pragma unroll
            for (int nt = 0; nt < 2; nt++) {
                long row = m0 + wm + mt * 16 + r;
                long col = n0 + wn + nt * 8 + cl * 2;
                float2 o0 = make_float2(cacc[mt][nt][0], cacc[mt][nt][1]);
                float2 o1 = make_float2(cacc[mt][nt][2], cacc[mt][nt][3]);
                if (Cacc) {
                    float2 p0 = *(const float2*)(Cacc + row * N + col);
                    float2 p1 = *(const float2*)(Cacc + (row + 8) * N + col);
                    o0.x += p0.x; o0.y += p0.y;
                    o1.x += p1.x; o1.y += p1.y;
                }
                *(float2*)(C + row * N + col) = o0;
                *(float2*)(C + (row + 8) * N + col) = o1;
            }
    } else {
        float* T = (float*)smraw;  // 64x67 = 17152 B <= 17920
        #pragma unroll
        for (int mt = 0; mt < 2; mt++)
            #pragma unroll
            for (int nt = 0; nt < 2; nt++) {
                int row = wm + mt * 16 + r;
                int col = wn + nt * 8 + cl * 2;
                T[row * 67 + col]           = cacc[mt][nt][0];
                T[row * 67 + col + 1]       = cacc[mt][nt][1];
                T[(row + 8) * 67 + col]     = cacc[mt][nt][2];
                T[(row + 8) * 67 + col + 1] = cacc[mt][nt][3];
            }
        __syncthreads();
        for (int i = tid; i < 4096; i += 256) {
            int ml = i >> 6, nl = i & 63;
            C[(long)(m0 + ml) * N + n0 + nl] = T[ml * 67 + nl];
        }
        for (int i = tid; i < 4096; i += 256) {
            int nl = i >> 6, ml = i & 63;
            float v = T[ml * 67 + nl];
            long off = (long)(n0 + nl) * M + m0 + ml;
            CT[off] = v;
            SigT[off] = 1.f / (1.f + expf(-v));
        }
    }
}

// yi from gram + column softmax
__global__ __launch_bounds__(256) void k_yis(const float* __restrict__ G,
                                             float* __restrict__ yis)
{
    __shared__ float red[9];
    int s = blockIdx.x, p = threadIdx.x;
    int sy = s >> 4, sx = s & 15;
    int py = p >> 4, px = p & 15;
    float raw = 0.f, nsum = 0.f;
    #pragma unroll
    for (int dy = -1; dy <= 1; dy++)
        #pragma unroll
        for (int dx = -1; dx <= 1; dx++) {
            int qy = py + dy, qx = px + dx;
            if (qy >= 0 && qy < 16 && qx >= 0 && qx < 16) {
                int q = qy * 16 + qx;
                nsum += G[q * 256 + q];
                int ry = sy + dy, rx = sx + dx;
                if (ry >= 0 && ry < 16 && rx >= 0 && rx < 16)
                    raw += G[q * 256 + ry * 16 + rx];
            }
        }
    float nrm = fmaxf(sqrtf(nsum), 1e-4f);
    float v = 10.f * raw / nrm;
    float mx = blockMax256(v, red);
    float e = expf(v - mx);
    float ssum = blockSum256(e, red);
    yis[p * 256 + s] = e / ssum;
}

// combined deconv matrix M[q][o]
__global__ __launch_bounds__(256) void k_buildM(const float* __restrict__ yis,
                                                float* __restrict__ Mm)
{
    int idx = blockIdx.x * 256 + threadIdx.x;
    int o = idx & 1023, q = idx >> 10;
    int oy = o >> 5, ox = o & 31;
    int qrow = q >> 5, qcol = q & 31;
    int kyv[2], syv[2], kxv[2], sxv[2];
    if (oy & 1) { kyv[0] = 1; syv[0] = (oy - 1) >> 1; kyv[1] = 3; syv[1] = (oy + 1) >> 1; }
    else        { kyv[0] = 0; syv[0] = (oy >> 1) - 1; kyv[1] = 2; syv[1] = oy >> 1; }
    if (ox & 1) { kxv[0] = 1; sxv[0] = (ox - 1) >> 1; kxv[1] = 3; sxv[1] = (ox + 1) >> 1; }
    else        { kxv[0] = 0; sxv[0] = (ox >> 1) - 1; kxv[1] = 2; sxv[1] = ox >> 1; }
    float acc = 0.f;
    #pragma unroll
    for (int a = 0; a < 2; a++) {
        if (syv[a] < 0 || syv[a] > 15) continue;
        int ty = qrow - 2 + kyv[a];
        if (ty < 0 || ty >= 32 || (ty & 1)) continue;
        int py = ty >> 1;
        #pragma unroll
        for (int b = 0; b < 2; b++) {
            if (sxv[b] < 0 || sxv[b] > 15) continue;
            int tx = qcol - 2 + kxv[b];
            if (tx < 0 || tx >= 32 || (tx & 1)) continue;
            acc += yis[(py * 16 + (tx >> 1)) * 256 + syv[a] * 16 + sxv[b]];
        }
    }
    Mm[idx] = 0.25f * acc;
}

// extract 1D gaussian rows: gxn[i*32+h] = sum_w gus[(i*32)*1024 + h*32 + w]
// grid 32 blocks x 32 threads (parallelized; was 1-block latency-bound)
__global__ void k_gxn(const float* __restrict__ gus, float* __restrict__ gxn)
{
    int i = blockIdx.x, h = threadIdx.x;
    const float* row = gus + (long)(i * 32) * 1024 + h * 32;
    float s = 0.f;
    #pragma unroll
    for (int w = 0; w < 32; w++) s += row[w];
    gxn[i * 32 + h] = s;
}

// exact separable gaussian blur
__global__ __launch_bounds__(256) void k_gus_blur(
    const float* __restrict__ ralout, const float* __restrict__ gxn,
    float* __restrict__ gusb)
{
    __shared__ float xsb[1024], gb[1024], t1[1024];
    int c = blockIdx.x, t = threadIdx.x;
    for (int i = t; i < 1024; i += 256) {
        xsb[i] = ralout[c * 1024 + i];
        gb[i]  = gxn[i];
    }
    __syncthreads();
    for (int i = t; i < 1024; i += 256) {
        int py = i >> 5, w = i & 31;
        float s = 0.f;
        #pragma unroll
        for (int h = 0; h < 32; h++) s += gb[py * 32 + h] * xsb[h * 32 + w];
        t1[i] = s;
    }
    __syncthreads();
    for (int i = t; i < 1024; i += 256) {
        int py = i >> 5, px = i & 31;
        float s = 0.f;
        #pragma unroll
        for (int w = 0; w < 32; w++) s += gb[px * 32 + w] * t1[py * 32 + w];
        gusb[(long)i * 512 + c] = s;
    }
}

// csa
__global__ __launch_bounds__(256) void k_csa(const float* __restrict__ sigT,
                                             const float* __restrict__ ralT,
                                             float* __restrict__ csab)
{
    __shared__ float ws[8][9];
    __shared__ float a9[9];
    int p = blockIdx.x, t = threadIdx.x;
    int lane = t & 31, w = t >> 5;
    int py = p >> 5, px = p & 31;
    int nb[9]; bool ok[9];
    #pragma unroll
    for (int d = 0; d < 9; d++) {
        int dy = d / 3 - 1, dx = d % 3 - 1;
        int y = py + dy, x = px + dx;
        ok[d] = (y >= 0 && y < 32 && x >= 0 && x < 32);
        nb[d] = ok[d] ? (y * 32 + x) : 0;
    }
    float loc[9] = {};
    for (int c = t; c < 512; c += 256) {
        float sv = sigT[p * 512 + c];
        #pragma unroll
        for (int d = 0; d < 9; d++)
            if (ok[d]) loc[d] += sv * sigT[nb[d] * 512 + c];
    }
    #pragma unroll
    for (int d = 0; d < 9; d++) {
        #pragma unroll
        for (int o = 16; o; o >>= 1) loc[d] += __shfl_down_sync(0xffffffffu, loc[d], o);
        if (lane == 0) ws[w][d] = loc[d];
    }
    __syncthreads();
    if (t < 9) {
        float s = 0.f;
        #pragma unroll
        for (int i = 0; i < 8; i++) s += ws[i][t];
        a9[t] = s * (1.f / 512.f);
    }
    __syncthreads();
    float mx = -1e30f;
    #pragma unroll
    for (int d = 0; d < 9; d++) mx = fmaxf(mx, a9[d]);
    float wgt[9]; float ssum = 0.f;
    #pragma unroll
    for (int d = 0; d < 9; d++) { wgt[d] = expf(a9[d] - mx); ssum += wgt[d]; }
    float inv = 1.f / ssum;
    for (int c = t; c < 512; c += 256) {
        float acc = 0.f;
        #pragma unroll
        for (int d = 0; d < 9; d++)
            if (ok[d]) acc += wgt[d] * ralT[nb[d] * 512 + c];
        csab[p * 512 + c] = acc * inv;
    }
}

// instance norm + leaky relu 0.2 (single input)
__global__ __launch_bounds__(256) void k_inorm_lrelu(const float* __restrict__ in,
                                                     float* __restrict__ out)
{
    __shared__ float red[9];
    int c = blockIdx.x, t = threadIdx.x;
    float v[4];
    #pragma unroll
    for (int q = 0; q < 4; q++) v[q] = in[c * 1024 + t + q * 256];
    float s  = v[0] + v[1] + v[2] + v[3];
    float sq = v[0]*v[0] + v[1]*v[1] + v[2]*v[2] + v[3]*v[3];
    s  = blockSum256(s,  red);
    sq = blockSum256(sq, red);
    float mean = s * (1.f / 1024.f);
    float var  = sq * (1.f / 1024.f) - mean * mean;
    float rstd = rsqrtf(var + 1e-5f);
    #pragma unroll
    for (int q = 0; q < 4; q++) {
        float z = (v[q] - mean) * rstd;
        out[c * 1024 + t + q * 256] = (z >= 0.f) ? z : 0.2f * z;
    }
}

// add two partials + instance norm + leaky relu 0.2
__global__ __launch_bounds__(256) void k_add_inorm_lrelu(
    const float* __restrict__ inA, const float* __restrict__ inB,
    float* __restrict__ out)
{
    __shared__ float red[9];
    int c = blockIdx.x, t = threadIdx.x;
    float v[4];
    #pragma unroll
    for (int q = 0; q < 4; q++) {
        long i = (long)c * 1024 + t + q * 256;
        v[q] = inA[i] + inB[i];
    }
    float s  = v[0] + v[1] + v[2] + v[3];
    float sq = v[0]*v[0] + v[1]*v[1] + v[2]*v[2] + v[3]*v[3];
    s  = blockSum256(s,  red);
    sq = blockSum256(sq, red);
    float mean = s * (1.f / 1024.f);
    float var  = sq * (1.f / 1024.f) - mean * mean;
    float rstd = rsqrtf(var + 1e-5f);
    #pragma unroll
    for (int q = 0; q < 4; q++) {
        float z = (v[q] - mean) * rstd;
        out[c * 1024 + t + q * 256] = (z >= 0.f) ? z : 0.2f * z;
    }
}

// ---------------------------------------------------------------------------
extern "C" void kernel_launch(void* const* d_in, const int* in_sizes, int n_in,
                              void* d_out, int out_size)
{
    const float* x      = (const float*)d_in[0];
    const float* gus    = (const float*)d_in[1];
    const float* w3     = (const float*)d_in[2];
    const float* w5     = (const float*)d_in[4];
    const float* w7     = (const float*)d_in[6];
    const float* fc_w   = (const float*)d_in[8];
    const float* fc_b   = (const float*)d_in[9];
    const float* fcs_w  = (const float*)d_in[10];
    const float* fcs_b  = (const float*)d_in[11];
    const float* down_w = (const float*)d_in[12];
    const float* fuse_w = (const float*)d_in[13];
    float* out = (float*)d_out;

    void* sp = nullptr;
    cudaGetSymbolAddress(&sp, g_scratch);
    float* S = (float*)sp;
    float* feas   = S + O_FEAS;
    float* y1rawB = S + O_FEAS;          // reuse: feas dead after mix
    float* bmean  = S + O_BMEAN;
    float* gxn    = S + O_GXN;
    float* outres = S + O_OUTRES;
    float* fdT    = S + O_FDT;
    float* G      = S + O_G;
    float* yis    = S + O_YIS;
    float* Mm     = S + O_MM;
    float* ralout = S + O_RALOUT;
    float* ralT   = S + O_RALT;
    float* sigT   = S + O_SIGT;
    float* gusb   = S + O_GUSB;
    float* csab   = S + O_CSAB;
    float* y1raw  = S + O_Y1RAW;
    float* y1     = S + O_Y1;
    float* y2raw  = S + O_Y2RAW;

    constexpr int SM3 = (16 * 9  * 4) * 4 + 16 * 34 * 36 * 4;  //  80640 B
    constexpr int SM5 = (16 * 25 * 4) * 4 + 16 * 36 * 36 * 4;  //  89344 B
    constexpr int SM7 = (16 * 49 * 4) * 4 + 16 * 38 * 40 * 4;  // 109824 B

    static cudaStream_t s1 = nullptr, s2 = nullptr;
    static cudaEvent_t evA, ev1, ev2, evM, ev5, evC, ev4;
    if (!s1) {
        cudaStreamCreateWithFlags(&s1, cudaStreamNonBlocking);
        cudaStreamCreateWithFlags(&s2, cudaStreamNonBlocking);
        cudaEventCreateWithFlags(&evA, cudaEventDisableTiming);
        cudaEventCreateWithFlags(&ev1, cudaEventDisableTiming);
        cudaEventCreateWithFlags(&ev2, cudaEventDisableTiming);
        cudaEventCreateWithFlags(&evM, cudaEventDisableTiming);
        cudaEventCreateWithFlags(&ev5, cudaEventDisableTiming);
        cudaEventCreateWithFlags(&evC, cudaEventDisableTiming);
        cudaEventCreateWithFlags(&ev4, cudaEventDisableTiming);
        cudaFuncSetAttribute(k_skconv<3>,
            cudaFuncAttributeMaxDynamicSharedMemorySize, SM3);
        cudaFuncSetAttribute(k_skconv<5>,
            cudaFuncAttributeMaxDynamicSharedMemorySize, SM5);
        cudaFuncSetAttribute(k_skconv<7>,
            cudaFuncAttributeMaxDynamicSharedMemorySize, SM7);
    }

    // fork: 3 conv kernels launch FIRST on their streams; gxn follows k7
    cudaEventRecord(evA, 0);
    cudaStreamWaitEvent(s1, evA, 0);
    cudaStreamWaitEvent(s2, evA, 0);
    k_skconv<3><<<128, 256, SM3, 0 >>>(x, w3, feas,           bmean);
    k_skconv<5><<<128, 256, SM5, s1>>>(x, w5, feas + 524288,  bmean + 512);
    k_skconv<7><<<128, 256, SM7, s2>>>(x, w7, feas + 1048576, bmean + 1024);
    k_gxn<<<32, 32, 0, s2>>>(gus, gxn);
    cudaEventRecord(ev1, s1);
    cudaEventRecord(ev2, s2);
    cudaStreamWaitEvent(0, ev1, 0);
    cudaStreamWaitEvent(0, ev2, 0);

    // fused fcz + attention + mix + fd (one block per channel)
    k_mix_att_fcz<<<512, 256>>>(feas, bmean, fc_w, fc_b, fcs_w, fcs_b,
                                outres, fdT);

    // early fuse-partial on s2: y2raw = fuse_w[:,512:] * outres
    cudaEventRecord(evM, 0);
    cudaStreamWaitEvent(s2, evM, 0);
    gemm3_ab<<<dim3(16, 8, 1), 256, 0, s2>>>(fuse_w + 512, 1024,
                                             outres, outres, 512, y2raw, nullptr,
                                             512, 1024, 512, nullptr, nullptr);
    cudaEventRecord(ev5, s2);

    k_gram<<<dim3(8, 8), 256>>>(fdT, G);
    k_yis<<<256, 256>>>(G, yis);
    k_buildM<<<4096, 256>>>(yis, Mm);
    gemm3_ab<<<dim3(16, 8, 1), 256>>>(outres, 1024, Mm, Mm, 1024, ralout,
                                      nullptr, 512, 1024, 1024, ralT, sigT);

    // fork: csa -> downB on s1 (separate buffer); blur -> downA on 0
    cudaEventRecord(evC, 0);
    cudaStreamWaitEvent(s1, evC, 0);
    k_csa<<<1024, 256, 0, s1>>>(sigT, ralT, csab);
    gemm3_ab<<<dim3(16, 8, 1), 256, 0, s1>>>(down_w + 512, 1024, csab, csab,
                                             512, y1rawB, nullptr,
                                             512, 1024, 512, nullptr, nullptr);
    cudaEventRecord(ev4, s1);
    k_gus_blur<<<512, 256>>>(ralout, gxn, gusb);
    gemm3_ab<<<dim3(16, 8, 1), 256>>>(down_w, 1024, gusb, gusb, 512, y1raw,
                                      nullptr, 512, 1024, 512, nullptr, nullptr);
    cudaStreamWaitEvent(0, ev4, 0);
    k_add_inorm_lrelu<<<512, 256>>>(y1raw, y1rawB, y1);

    // fuse-final: y2raw += fuse_w[:,:512] * y1
    cudaStreamWaitEvent(0, ev5, 0);
    gemm3_ab<<<dim3(16, 8, 1), 256>>>(fuse_w, 1024, y1, y1, 512, y2raw,
                                      y2raw, 512, 1024, 512, nullptr, nullptr);
    k_inorm_lrelu<<<512, 256>>>(y2raw, out);
}

// round 17
// speedup vs baseline: 1.1717x; 1.0075x over previous
#include <cuda_runtime.h>
#include <math.h>

static constexpr long O_FEAS   = 0;            // reused as y1rawB after mix
static constexpr long O_BMEAN  = 1572864;
static constexpr long O_GXN    = 1574400;      // 1024
static constexpr long O_OUTRES = 1575936;
static constexpr long O_FDT    = 2100224;
static constexpr long O_G      = 2231296;
static constexpr long O_YIS    = 2297088;
static constexpr long O_MM     = 2362624;
static constexpr long O_RALOUT = 6556928;
static constexpr long O_RALT   = 7081216;
static constexpr long O_SIGT   = 7605504;
static constexpr long O_GUSB   = 8129792;
static constexpr long O_CSAB   = 8654080;
static constexpr long O_Y1RAW  = 9178368;
static constexpr long O_Y1     = 9702656;
static constexpr long O_Y2RAW  = 10226944;
static constexpr long SCRATCH  = 10751232;

__device__ __align__(256) float g_scratch[SCRATCH];

__device__ __forceinline__ float blockSum256(float v, float* red) {
    int lane = threadIdx.x & 31, w = threadIdx.x >> 5;
    #pragma unroll
    for (int o = 16; o; o >>= 1) v += __shfl_down_sync(0xffffffffu, v, o);
    if (lane == 0) red[w] = v;
    __syncthreads();
    if (threadIdx.x == 0) {
        float s = 0.f;
        #pragma unroll
        for (int i = 0; i < 8; i++) s += red[i];
        red[8] = s;
    }
    __syncthreads();
    return red[8];
}
__device__ __forceinline__ float blockMax256(float v, float* red) {
    int lane = threadIdx.x & 31, w = threadIdx.x >> 5;
    #pragma unroll
    for (int o = 16; o; o >>= 1) v = fmaxf(v, __shfl_down_sync(0xffffffffu, v, o));
    if (lane == 0) red[w] = v;
    __syncthreads();
    if (threadIdx.x == 0) {
        float s = red[0];
        #pragma unroll
        for (int i = 1; i < 8; i++) s = fmaxf(s, red[i]);
        red[8] = s;
    }
    __syncthreads();
    return red[8];
}

__device__ __forceinline__ unsigned cvt_tf32(float x) {
    unsigned r;
    asm("cvt.rna.tf32.f32 %0, %1;" : "=r"(r) : "f"(x));
    return r;
}
__device__ __forceinline__ void mma_tf32(float c[4], const unsigned a[4],
                                         const unsigned b[2]) {
    asm volatile(
        "mma.sync.aligned.m16n8k8.row.col.f32.tf32.tf32.f32 "
        "{%0,%1,%2,%3},{%4,%5,%6,%7},{%8,%9},{%0,%1,%2,%3};"
        : "+f"(c[0]), "+f"(c[1]), "+f"(c[2]), "+f"(c[3])
        : "r"(a[0]), "r"(a[1]), "r"(a[2]), "r"(a[3]), "r"(b[0]), "r"(b[1]));
}

// ---------------------------------------------------------------------------
// 1) Grouped conv + inorm + relu + mean, OC4-blocked, all 16 input channels
//    resident, one barrier, padded row stride for vectorized window loads.
//    (Verified: k7 = 38.6us, near fp32 FMA-issue floor.)
// ---------------------------------------------------------------------------
template <int KW>
__global__ __launch_bounds__(256) void k_skconv(
    const float* __restrict__ x, const float* __restrict__ w,
    float* __restrict__ fea, float* __restrict__ bmean)
{
    constexpr int PAD  = (KW - 1) / 2;
    constexpr int S    = 32 + 2 * PAD;
    constexpr int SP   = (S + 3) & ~3;
    constexpr int TAPS = KW * KW;
    extern __shared__ float sm[];
    float* wsm = sm;
    float* xt  = sm + 16 * TAPS * 4;
    __shared__ float red[9];

    const int g   = blockIdx.x >> 2;
    const int oc0 = g * 16 + (blockIdx.x & 3) * 4;
    const int t   = threadIdx.x;
    const int py  = t >> 3;
    const int tx4 = (t & 7) * 4;

    for (int i = t; i < 16 * TAPS * 4; i += 256) {
        int l = i & 3, rest = i >> 2;
        wsm[i] = w[(long)(oc0 + l) * (16 * TAPS) + rest];
    }
    for (int i = t; i < 16 * S * SP; i += 256) xt[i] = 0.f;
    __syncthreads();
    const float* xg = x + (long)g * 16 * 1024;
    for (int i = t; i < 16 * 1024; i += 256) {
        int ci = i >> 10, p = i & 1023;
        int r = p >> 5, c = p & 31;
        xt[ci * S * SP + (r + PAD) * SP + (c + PAD)] = xg[i];
    }
    __syncthreads();

    float acc[4][4] = {};
    for (int ci = 0; ci < 16; ci++) {
        const float* base = xt + ci * S * SP;
        const float4* wq = (const float4*)wsm + ci * TAPS;
        #pragma unroll
        for (int ky = 0; ky < KW; ky++) {
            const float* xr = base + (py + ky) * SP + tx4;
            float xv[KW + 3];
            #pragma unroll
            for (int j4 = 0; j4 < (KW + 3) / 4; j4++) {
                float4 v = *(const float4*)(xr + j4 * 4);
                xv[j4 * 4 + 0] = v.x; xv[j4 * 4 + 1] = v.y;
                xv[j4 * 4 + 2] = v.z; xv[j4 * 4 + 3] = v.w;
            }
            if constexpr (((KW + 3) & 3) == 2) {
                float2 v = *(const float2*)(xr + ((KW + 3) & ~3));
                xv[(KW + 3) & ~3]       = v.x;
                xv[((KW + 3) & ~3) + 1] = v.y;
            }
            #pragma unroll
            for (int kx = 0; kx < KW; kx++) {
                float4 wv = wq[ky * KW + kx];
                acc[0][0] = fmaf(wv.x, xv[kx    ], acc[0][0]);
                acc[0][1] = fmaf(wv.x, xv[kx + 1], acc[0][1]);
                acc[0][2] = fmaf(wv.x, xv[kx + 2], acc[0][2]);
                acc[0][3] = fmaf(wv.x, xv[kx + 3], acc[0][3]);
                acc[1][0] = fmaf(wv.y, xv[kx    ], acc[1][0]);
                acc[1][1] = fmaf(wv.y, xv[kx + 1], acc[1][1]);
                acc[1][2] = fmaf(wv.y, xv[kx + 2], acc[1][2]);
                acc[1][3] = fmaf(wv.y, xv[kx + 3], acc[1][3]);
                acc[2][0] = fmaf(wv.z, xv[kx    ], acc[2][0]);
                acc[2][1] = fmaf(wv.z, xv[kx + 1], acc[2][1]);
                acc[2][2] = fmaf(wv.z, xv[kx + 2], acc[2][2]);
                acc[2][3] = fmaf(wv.z, xv[kx + 3], acc[2][3]);
                acc[3][0] = fmaf(wv.w, xv[kx    ], acc[3][0]);
                acc[3][1] = fmaf(wv.w, xv[kx + 1], acc[3][1]);
                acc[3][2] = fmaf(wv.w, xv[kx + 2], acc[3][2]);
                acc[3][3] = fmaf(wv.w, xv[kx + 3], acc[3][3]);
            }
        }
    }
    __syncthreads();
    #pragma unroll
    for (int l = 0; l < 4; l++) {
        float s  = acc[l][0] + acc[l][1] + acc[l][2] + acc[l][3];
        float sq = acc[l][0]*acc[l][0] + acc[l][1]*acc[l][1]
                 + acc[l][2]*acc[l][2] + acc[l][3]*acc[l][3];
        s  = blockSum256(s,  red);
        sq = blockSum256(sq, red);
        float mean = s * (1.f / 1024.f);
        float var  = sq * (1.f / 1024.f) - mean * mean;
        float rstd = rsqrtf(var + 1e-5f);
        float v0 = fmaxf((acc[l][0] - mean) * rstd, 0.f);
        float v1 = fmaxf((acc[l][1] - mean) * rstd, 0.f);
        float v2 = fmaxf((acc[l][2] - mean) * rstd, 0.f);
        float v3 = fmaxf((acc[l][3] - mean) * rstd, 0.f);
        *(float4*)(fea + (long)(oc0 + l) * 1024 + py * 32 + tx4) =
            make_float4(v0, v1, v2, v3);
        float rsum = blockSum256(v0 + v1 + v2 + v3, red);
        if (t == 0) bmean[oc0 + l] = rsum * (1.f / 1024.f);
    }
}

// 2+3) fused: fea_z FC + attention softmax + mix + downsample-transpose.
__global__ __launch_bounds__(256) void k_mix_att_fcz(
    const float* __restrict__ feas, const float* __restrict__ bmean,
    const float* __restrict__ fc_w, const float* __restrict__ fc_b,
    const float* __restrict__ fcs_w, const float* __restrict__ fcs_b,
    float* __restrict__ outres, float* __restrict__ fdT)
{
    __shared__ float ssum[512];
    __shared__ float sz[32];
    int t = threadIdx.x, c = blockIdx.x;
    int lane = t & 31, w = t >> 5;
    for (int i = t; i < 512; i += 256)
        ssum[i] = bmean[i] + bmean[512 + i] + bmean[1024 + i];
    __syncthreads();
    #pragma unroll
    for (int dd = 0; dd < 4; dd++) {
        int d = w * 4 + dd;
        float a = 0.f;
        const float* fw = fc_w + d * 512;
        for (int ch = lane; ch < 512; ch += 32) a += ssum[ch] * fw[ch];
        #pragma unroll
        for (int o = 16; o; o >>= 1) a += __shfl_down_sync(0xffffffffu, a, o);
        if (lane == 0) sz[d] = a + fc_b[d];
    }
    __syncthreads();
    float av[3];
    #pragma unroll
    for (int m = 0; m < 3; m++) {
        float a = fcs_b[m * 512 + c];
        const float* fw = fcs_w + (m * 512 + c) * 32;
        #pragma unroll
        for (int d = 0; d < 32; d++) a += sz[d] * fw[d];
        av[m] = a;
    }
    float mx = fmaxf(av[0], fmaxf(av[1], av[2]));
    float e0 = expf(av[0] - mx), e1 = expf(av[1] - mx), e2 = expf(av[2] - mx);
    float inv = 1.f / (e0 + e1 + e2);
    #pragma unroll
    for (int qq = 0; qq < 4; qq++) {
        int o = t + qq * 256;
        long idx = (long)c * 1024 + o;
        float v = (e0 * feas[idx] + e1 * feas[524288 + idx]
                 + e2 * feas[1048576 + idx]) * inv;
        outres[idx] = v;
        int oy = o >> 5, ox = o & 31;
        if (!(oy & 1) && !(ox & 1))
            fdT[((oy >> 1) * 16 + (ox >> 1)) * 512 + c] = v;
    }
}

// gram (fp32, feeds exp): 256x256, K=512, 32x32 tiles
__global__ __launch_bounds__(256) void k_gram(const float* __restrict__ A,
                                              float* __restrict__ C)
{
    __shared__ float As[16][36];
    __shared__ float Bs[16][36];
    int tid = threadIdx.x;
    int m0 = blockIdx.y * 32, n0 = blockIdx.x * 32;
    int tx = tid & 15, ty = tid >> 4;
    int lm = (tid & 127) >> 2, lk4 = (tid & 3) * 4;
    float acc[2][2] = {};
    for (int kt = 0; kt < 512; kt += 16) {
        if (tid < 128) {
            float4 v = *(const float4*)(A + (long)(m0 + lm) * 512 + kt + lk4);
            As[lk4 + 0][lm] = v.x; As[lk4 + 1][lm] = v.y;
            As[lk4 + 2][lm] = v.z; As[lk4 + 3][lm] = v.w;
        } else {
            float4 v = *(const float4*)(A + (long)(n0 + lm) * 512 + kt + lk4);
            Bs[lk4 + 0][lm] = v.x; Bs[lk4 + 1][lm] = v.y;
            Bs[lk4 + 2][lm] = v.z; Bs[lk4 + 3][lm] = v.w;
        }
        __syncthreads();
        #pragma unroll
        for (int kk = 0; kk < 16; kk++) {
            float a0 = As[kk][ty * 2], a1 = As[kk][ty * 2 + 1];
            float b0 = Bs[kk][tx * 2], b1 = Bs[kk][tx * 2 + 1];
            acc[0][0] += a0 * b0; acc[0][1] += a0 * b1;
            acc[1][0] += a1 * b0; acc[1][1] += a1 * b1;
        }
        __syncthreads();
    }
    int m = m0 + ty * 2, n = n0 + tx * 2;
    C[m * 256 + n] = acc[0][0];       C[m * 256 + n + 1] = acc[0][1];
    C[(m + 1) * 256 + n] = acc[1][0]; C[(m + 1) * 256 + n + 1] = acc[1][1];
}

// ---------------------------------------------------------------------------
// 3xTF32 GEMM: uint2-packed hi/lo smem, term-major mmas.
// ---------------------------------------------------------------------------
__global__ __launch_bounds__(256) void gemm3_ab(
    const float* __restrict__ A, int lda,
    const float* __restrict__ B1, const float* __restrict__ B2, int K1,
    float* __restrict__ C, const float* __restrict__ Cacc,
    int M, int N, int K, float* __restrict__ CT, float* __restrict__ SigT)
{
    __shared__ __align__(16) char smraw[2 * 16 * 70 * 8];
    uint2 (*As)[70] = (uint2(*)[70])smraw;
    uint2 (*Bs)[70] = (uint2(*)[70])(smraw + 16 * 70 * 8);
    int tid = threadIdx.x;
    int lane = tid & 31, wid = tid >> 5;
    int wm = (wid >> 2) * 32, wn = (wid & 3) * 16;
    int m0 = blockIdx.y * 64, n0 = blockIdx.x * 64;
    int a_m = tid >> 2, a_k4 = (tid & 3) * 4;
    int b_k = tid >> 4, b_n4 = (tid & 15) * 4;
    int r = lane >> 2, cl = lane & 3;
    float cacc[2][2][4] = {};

    const float* aptr = A + (long)(m0 + a_m) * lda + a_k4;
    float4 av = *(const float4*)(aptr);
    const float* bs0 = (b_k < K1) ? (B1 + (long)b_k * N) : (B2 + (long)(b_k - K1) * N);
    float4 bv = *(const float4*)(bs0 + n0 + b_n4);

    for (int kt = 0; kt < K; kt += 16) {
        float va[4] = {av.x, av.y, av.z, av.w};
        float vb[4] = {bv.x, bv.y, bv.z, bv.w};
        #pragma unroll
        for (int i = 0; i < 4; i++) {
            unsigned h = cvt_tf32(va[i]);
            As[a_k4 + i][a_m] = make_uint2(h, cvt_tf32(va[i] - __uint_as_float(h)));
            unsigned g = cvt_tf32(vb[i]);
            Bs[b_k][b_n4 + i] = make_uint2(g, cvt_tf32(vb[i] - __uint_as_float(g)));
        }
        __syncthreads();
        if (kt + 16 < K) {
            av = *(const float4*)(aptr + kt + 16);
            int gk = kt + 16 + b_k;
            const float* src = (gk < K1) ? (B1 + (long)gk * N) : (B2 + (long)(gk - K1) * N);
            bv = *(const float4*)(src + n0 + b_n4);
        }
        #pragma unroll
        for (int ks = 0; ks < 16; ks += 8) {
            unsigned ah[2][4], al[2][4], bh[2][2], bl[2][2];
            #pragma unroll
            for (int mt = 0; mt < 2; mt++) {
                int mb = wm + mt * 16 + r;
                uint2 q0 = As[ks + cl][mb];
                uint2 q1 = As[ks + cl][mb + 8];
                uint2 q2 = As[ks + cl + 4][mb];
                uint2 q3 = As[ks + cl + 4][mb + 8];
                ah[mt][0] = q0.x; ah[mt][1] = q1.x; ah[mt][2] = q2.x; ah[mt][3] = q3.x;
                al[mt][0] = q0.y; al[mt][1] = q1.y; al[mt][2] = q2.y; al[mt][3] = q3.y;
            }
            #pragma unroll
            for (int nt = 0; nt < 2; nt++) {
                int nb = wn + nt * 8 + r;
                uint2 u0 = Bs[ks + cl][nb];
                uint2 u1 = Bs[ks + cl + 4][nb];
                bh[nt][0] = u0.x; bh[nt][1] = u1.x;
                bl[nt][0] = u0.y; bl[nt][1] = u1.y;
            }
            #pragma unroll
            for (int mt = 0; mt < 2; mt++)
                #pragma unroll
                for (int nt = 0; nt < 2; nt++) mma_tf32(cacc[mt][nt], ah[mt], bl[nt]);
            #pragma unroll
            for (int mt = 0; mt < 2; mt++)
                #pragma unroll
                for (int nt = 0; nt < 2; nt++) mma_tf32(cacc[mt][nt], al[mt], bh[nt]);
            #pragma unroll
            for (int mt = 0; mt < 2; mt++)
                #pragma unroll
                for (int nt = 0; nt < 2; nt++) mma_tf32(cacc[mt][nt], ah[mt], bh[nt]);
        }
        __syncthreads();
    }
    if (CT == nullptr) {
        #pragma unroll
        for (int mt = 0; mt < 2; mt++)
            #pragma unroll
            for (int nt = 0; nt < 2; nt++) {
                long row = m0 + wm + mt * 16 + r;
                long col = n0 + wn + nt * 8 + cl * 2;
                float2 o0 = make_float2(cacc[mt][nt][0], cacc[mt][nt][1]);
                float2 o1 = make_float2(cacc[mt][nt][2], cacc[mt][nt][3]);
                if (Cacc) {
                    float2 p0 = *(const float2*)(Cacc + row * N + col);
                    float2 p1 = *(const float2*)(Cacc + (row + 8) * N + col);
                    o0.x += p0.x; o0.y += p0.y;
                    o1.x += p1.x; o1.y += p1.y;
                }
                *(float2*)(C + row * N + col) = o0;
                *(float2*)(C + (row + 8) * N + col) = o1;
            }
    } else {
        float* T = (float*)smraw;  // 64x67 = 17152 B <= 17920
        #pragma unroll
        for (int mt = 0; mt < 2; mt++)
            #pragma unroll
            for (int nt = 0; nt < 2; nt++) {
                int row = wm + mt * 16 + r;
                int col = wn + nt * 8 + cl * 2;
                T[row * 67 + col]           = cacc[mt][nt][0];
                T[row * 67 + col + 1]       = cacc[mt][nt][1];
                T[(row + 8) * 67 + col]     = cacc[mt][nt][2];
                T[(row + 8) * 67 + col + 1] = cacc[mt][nt][3];
            }
        __syncthreads();
        for (int i = tid; i < 4096; i += 256) {
            int ml = i >> 6, nl = i & 63;
            C[(long)(m0 + ml) * N + n0 + nl] = T[ml * 67 + nl];
        }
        for (int i = tid; i < 4096; i += 256) {
            int nl = i >> 6, ml = i & 63;
            float v = T[ml * 67 + nl];
            long off = (long)(n0 + nl) * M + m0 + ml;
            CT[off] = v;
            SigT[off] = 1.f / (1.f + expf(-v));
        }
    }
}

// yi from gram + column softmax
__global__ __launch_bounds__(256) void k_yis(const float* __restrict__ G,
                                             float* __restrict__ yis)
{
    __shared__ float red[9];
    int s = blockIdx.x, p = threadIdx.x;
    int sy = s >> 4, sx = s & 15;
    int py = p >> 4, px = p & 15;
    float raw = 0.f, nsum = 0.f;
    #pragma unroll
    for (int dy = -1; dy <= 1; dy++)
        #pragma unroll
        for (int dx = -1; dx <= 1; dx++) {
            int qy = py + dy, qx = px + dx;
            if (qy >= 0 && qy < 16 && qx >= 0 && qx < 16) {
                int q = qy * 16 + qx;
                nsum += G[q * 256 + q];
                int ry = sy + dy, rx = sx + dx;
                if (ry >= 0 && ry < 16 && rx >= 0 && rx < 16)
                    raw += G[q * 256 + ry * 16 + rx];
            }
        }
    float nrm = fmaxf(sqrtf(nsum), 1e-4f);
    float v = 10.f * raw / nrm;
    float mx = blockMax256(v, red);
    float e = expf(v - mx);
    float ssum = blockSum256(e, red);
    yis[p * 256 + s] = e / ssum;
}

// combined deconv matrix M[q][o]
__global__ __launch_bounds__(256) void k_buildM(const float* __restrict__ yis,
                                                float* __restrict__ Mm)
{
    int idx = blockIdx.x * 256 + threadIdx.x;
    int o = idx & 1023, q = idx >> 10;
    int oy = o >> 5, ox = o & 31;
    int qrow = q >> 5, qcol = q & 31;
    int kyv[2], syv[2], kxv[2], sxv[2];
    if (oy & 1) { kyv[0] = 1; syv[0] = (oy - 1) >> 1; kyv[1] = 3; syv[1] = (oy + 1) >> 1; }
    else        { kyv[0] = 0; syv[0] = (oy >> 1) - 1; kyv[1] = 2; syv[1] = oy >> 1; }
    if (ox & 1) { kxv[0] = 1; sxv[0] = (ox - 1) >> 1; kxv[1] = 3; sxv[1] = (ox + 1) >> 1; }
    else        { kxv[0] = 0; sxv[0] = (ox >> 1) - 1; kxv[1] = 2; sxv[1] = ox >> 1; }
    float acc = 0.f;
    #pragma unroll
    for (int a = 0; a < 2; a++) {
        if (syv[a] < 0 || syv[a] > 15) continue;
        int ty = qrow - 2 + kyv[a];
        if (ty < 0 || ty >= 32 || (ty & 1)) continue;
        int py = ty >> 1;
        #pragma unroll
        for (int b = 0; b < 2; b++) {
            if (sxv[b] < 0 || sxv[b] > 15) continue;
            int tx = qcol - 2 + kxv[b];
            if (tx < 0 || tx >= 32 || (tx & 1)) continue;
            acc += yis[(py * 16 + (tx >> 1)) * 256 + syv[a] * 16 + sxv[b]];
        }
    }
    Mm[idx] = 0.25f * acc;
}

// extract 1D gaussian rows (parallel 32x32)
__global__ void k_gxn(const float* __restrict__ gus, float* __restrict__ gxn)
{
    int i = blockIdx.x, h = threadIdx.x;
    const float* row = gus + (long)(i * 32) * 1024 + h * 32;
    float s = 0.f;
    #pragma unroll
    for (int w = 0; w < 32; w++) s += row[w];
    gxn[i * 32 + h] = s;
}

// exact separable gaussian blur
__global__ __launch_bounds__(256) void k_gus_blur(
    const float* __restrict__ ralout, const float* __restrict__ gxn,
    float* __restrict__ gusb)
{
    __shared__ float xsb[1024], gb[1024], t1[1024];
    int c = blockIdx.x, t = threadIdx.x;
    for (int i = t; i < 1024; i += 256) {
        xsb[i] = ralout[c * 1024 + i];
        gb[i]  = gxn[i];
    }
    __syncthreads();
    for (int i = t; i < 1024; i += 256) {
        int py = i >> 5, w = i & 31;
        float s = 0.f;
        #pragma unroll
        for (int h = 0; h < 32; h++) s += gb[py * 32 + h] * xsb[h * 32 + w];
        t1[i] = s;
    }
    __syncthreads();
    for (int i = t; i < 1024; i += 256) {
        int py = i >> 5, px = i & 31;
        float s = 0.f;
        #pragma unroll
        for (int w = 0; w < 32; w++) s += gb[px * 32 + w] * t1[py * 32 + w];
        gusb[(long)i * 512 + c] = s;
    }
}

// csa, pixel-paired: one block handles 2 x-adjacent pixels (pA even, pB=pA+1).
// Neighborhood union is 3 rows x 4 cols; invalid taps contribute 0 (matches
// zero-padded reference patches). Grid 512.
__global__ __launch_bounds__(256) void k_csa(const float* __restrict__ sigT,
                                             const float* __restrict__ ralT,
                                             float* __restrict__ csab)
{
    __shared__ float ws[8][18];
    __shared__ float a18[18];
    int p2 = blockIdx.x, t = threadIdx.x;
    int lane = t & 31, w = t >> 5;
    int pA = p2 * 2;
    int py = pA >> 5, px = pA & 31;          // px even, 0..30
    int nb[12]; bool ok[12];
    #pragma unroll
    for (int d = 0; d < 12; d++) {
        int dy = d / 4 - 1, dx = d % 4 - 1;  // dx -1..2
        int y = py + dy, x = px + dx;
        ok[d] = (y >= 0 && y < 32 && x >= 0 && x < 32);
        nb[d] = ok[d] ? (y * 32 + x) : 0;
    }
    float loc[18] = {};
    for (int c = t; c < 512; c += 256) {
        float nv[12];
        #pragma unroll
        for (int d = 0; d < 12; d++)
            nv[d] = ok[d] ? sigT[(long)nb[d] * 512 + c] : 0.f;
        float svA = nv[5];   // dy=0,dx=0
        float svB = nv[6];   // dy=0,dx=1
        #pragma unroll
        for (int j = 0; j < 9; j++) {
            int base = (j / 3) * 4 + (j % 3);
            loc[j]     += svA * nv[base];
            loc[9 + j] += svB * nv[base + 1];
        }
    }
    #pragma unroll
    for (int d = 0; d < 18; d++) {
        #pragma unroll
        for (int o = 16; o; o >>= 1) loc[d] += __shfl_down_sync(0xffffffffu, loc[d], o);
        if (lane == 0) ws[w][d] = loc[d];
    }
    __syncthreads();
    if (t < 18) {
        float s = 0.f;
        #pragma unroll
        for (int i = 0; i < 8; i++) s += ws[i][t];
        a18[t] = s * (1.f / 512.f);
    }
    __syncthreads();
    float mxA = -1e30f, mxB = -1e30f;
    #pragma unroll
    for (int j = 0; j < 9; j++) {
        mxA = fmaxf(mxA, a18[j]);
        mxB = fmaxf(mxB, a18[9 + j]);
    }
    float wgtA[9], wgtB[9], sA = 0.f, sB = 0.f;
    #pragma unroll
    for (int j = 0; j < 9; j++) {
        wgtA[j] = expf(a18[j] - mxA);     sA += wgtA[j];
        wgtB[j] = expf(a18[9 + j] - mxB); sB += wgtB[j];
    }
    float invA = 1.f / sA, invB = 1.f / sB;
    for (int c = t; c < 512; c += 256) {
        float rv[12];
        #pragma unroll
        for (int d = 0; d < 12; d++)
            rv[d] = ok[d] ? ralT[(long)nb[d] * 512 + c] : 0.f;
        float accA = 0.f, accB = 0.f;
        #pragma unroll
        for (int j = 0; j < 9; j++) {
            int base = (j / 3) * 4 + (j % 3);
            accA = fmaf(wgtA[j], rv[base], accA);
            accB = fmaf(wgtB[j], rv[base + 1], accB);
        }
        csab[(long)pA * 512 + c]       = accA * invA;
        csab[(long)(pA + 1) * 512 + c] = accB * invB;
    }
}

// instance norm + leaky relu 0.2 (single input)
__global__ __launch_bounds__(256) void k_inorm_lrelu(const float* __restrict__ in,
                                                     float* __restrict__ out)
{
    __shared__ float red[9];
    int c = blockIdx.x, t = threadIdx.x;
    float v[4];
    #pragma unroll
    for (int q = 0; q < 4; q++) v[q] = in[c * 1024 + t + q * 256];
    float s  = v[0] + v[1] + v[2] + v[3];
    float sq = v[0]*v[0] + v[1]*v[1] + v[2]*v[2] + v[3]*v[3];
    s  = blockSum256(s,  red);
    sq = blockSum256(sq, red);
    float mean = s * (1.f / 1024.f);
    float var  = sq * (1.f / 1024.f) - mean * mean;
    float rstd = rsqrtf(var + 1e-5f);
    #pragma unroll
    for (int q = 0; q < 4; q++) {
        float z = (v[q] - mean) * rstd;
        out[c * 1024 + t + q * 256] = (z >= 0.f) ? z : 0.2f * z;
    }
}

// add two partials + instance norm + leaky relu 0.2
__global__ __launch_bounds__(256) void k_add_inorm_lrelu(
    const float* __restrict__ inA, const float* __restrict__ inB,
    float* __restrict__ out)
{
    __shared__ float red[9];
    int c = blockIdx.x, t = threadIdx.x;
    float v[4];
    #pragma unroll
    for (int q = 0; q < 4; q++) {
        long i = (long)c * 1024 + t + q * 256;
        v[q] = inA[i] + inB[i];
    }
    float s  = v[0] + v[1] + v[2] + v[3];
    float sq = v[0]*v[0] + v[1]*v[1] + v[2]*v[2] + v[3]*v[3];
    s  = blockSum256(s,  red);
    sq = blockSum256(sq, red);
    float mean = s * (1.f / 1024.f);
    float var  = sq * (1.f / 1024.f) - mean * mean;
    float rstd = rsqrtf(var + 1e-5f);
    #pragma unroll
    for (int q = 0; q < 4; q++) {
        float z = (v[q] - mean) * rstd;
        out[c * 1024 + t + q * 256] = (z >= 0.f) ? z : 0.2f * z;
    }
}

// ---------------------------------------------------------------------------
extern "C" void kernel_launch(void* const* d_in, const int* in_sizes, int n_in,
                              void* d_out, int out_size)
{
    const float* x      = (const float*)d_in[0];
    const float* gus    = (const float*)d_in[1];
    const float* w3     = (const float*)d_in[2];
    const float* w5     = (const float*)d_in[4];
    const float* w7     = (const float*)d_in[6];
    const float* fc_w   = (const float*)d_in[8];
    const float* fc_b   = (const float*)d_in[9];
    const float* fcs_w  = (const float*)d_in[10];
    const float* fcs_b  = (const float*)d_in[11];
    const float* down_w = (const float*)d_in[12];
    const float* fuse_w = (const float*)d_in[13];
    float* out = (float*)d_out;

    void* sp = nullptr;
    cudaGetSymbolAddress(&sp, g_scratch);
    float* S = (float*)sp;
    float* feas   = S + O_FEAS;
    float* y1rawB = S + O_FEAS;          // reuse: feas dead after mix
    float* bmean  = S + O_BMEAN;
    float* gxn    = S + O_GXN;
    float* outres = S + O_OUTRES;
    float* fdT    = S + O_FDT;
    float* G      = S + O_G;
    float* yis    = S + O_YIS;
    float* Mm     = S + O_MM;
    float* ralout = S + O_RALOUT;
    float* ralT   = S + O_RALT;
    float* sigT   = S + O_SIGT;
    float* gusb   = S + O_GUSB;
    float* csab   = S + O_CSAB;
    float* y1raw  = S + O_Y1RAW;
    float* y1     = S + O_Y1;
    float* y2raw  = S + O_Y2RAW;

    constexpr int SM3 = (16 * 9  * 4) * 4 + 16 * 34 * 36 * 4;  //  80640 B
    constexpr int SM5 = (16 * 25 * 4) * 4 + 16 * 36 * 36 * 4;  //  89344 B
    constexpr int SM7 = (16 * 49 * 4) * 4 + 16 * 38 * 40 * 4;  // 109824 B

    static cudaStream_t s1 = nullptr, s2 = nullptr;
    static cudaEvent_t evA, ev1, ev2, evM, ev5, evC, ev4;
    if (!s1) {
        cudaStreamCreateWithFlags(&s1, cudaStreamNonBlocking);
        cudaStreamCreateWithFlags(&s2, cudaStreamNonBlocking);
        cudaEventCreateWithFlags(&evA, cudaEventDisableTiming);
        cudaEventCreateWithFlags(&ev1, cudaEventDisableTiming);
        cudaEventCreateWithFlags(&ev2, cudaEventDisableTiming);
        cudaEventCreateWithFlags(&evM, cudaEventDisableTiming);
        cudaEventCreateWithFlags(&ev5, cudaEventDisableTiming);
        cudaEventCreateWithFlags(&evC, cudaEventDisableTiming);
        cudaEventCreateWithFlags(&ev4, cudaEventDisableTiming);
        cudaFuncSetAttribute(k_skconv<3>,
            cudaFuncAttributeMaxDynamicSharedMemorySize, SM3);
        cudaFuncSetAttribute(k_skconv<5>,
            cudaFuncAttributeMaxDynamicSharedMemorySize, SM5);
        cudaFuncSetAttribute(k_skconv<7>,
            cudaFuncAttributeMaxDynamicSharedMemorySize, SM7);
    }

    // fork: 3 conv kernels launch FIRST on their streams; gxn follows k7
    cudaEventRecord(evA, 0);
    cudaStreamWaitEvent(s1, evA, 0);
    cudaStreamWaitEvent(s2, evA, 0);
    k_skconv<3><<<128, 256, SM3, 0 >>>(x, w3, feas,           bmean);
    k_skconv<5><<<128, 256, SM5, s1>>>(x, w5, feas + 524288,  bmean + 512);
    k_skconv<7><<<128, 256, SM7, s2>>>(x, w7, feas + 1048576, bmean + 1024);
    k_gxn<<<32, 32, 0, s2>>>(gus, gxn);
    cudaEventRecord(ev1, s1);
    cudaEventRecord(ev2, s2);
    cudaStreamWaitEvent(0, ev1, 0);
    cudaStreamWaitEvent(0, ev2, 0);

    // fused fcz + attention + mix + fd (one block per channel)
    k_mix_att_fcz<<<512, 256>>>(feas, bmean, fc_w, fc_b, fcs_w, fcs_b,
                                outres, fdT);

    // early fuse-partial on s2: y2raw = fuse_w[:,512:] * outres
    cudaEventRecord(evM, 0);
    cudaStreamWaitEvent(s2, evM, 0);
    gemm3_ab<<<dim3(16, 8, 1), 256, 0, s2>>>(fuse_w + 512, 1024,
                                             outres, outres, 512, y2raw, nullptr,
                                             512, 1024, 512, nullptr, nullptr);
    cudaEventRecord(ev5, s2);

    k_gram<<<dim3(8, 8), 256>>>(fdT, G);
    k_yis<<<256, 256>>>(G, yis);
    k_buildM<<<4096, 256>>>(yis, Mm);
    gemm3_ab<<<dim3(16, 8, 1), 256>>>(outres, 1024, Mm, Mm, 1024, ralout,
                                      nullptr, 512, 1024, 1024, ralT, sigT);

    // fork: csa -> downB on s1 (separate buffer); blur -> downA on 0
    cudaEventRecord(evC, 0);
    cudaStreamWaitEvent(s1, evC, 0);
    k_csa<<<512, 256, 0, s1>>>(sigT, ralT, csab);
    gemm3_ab<<<dim3(16, 8, 1), 256, 0, s1>>>(down_w + 512, 1024, csab, csab,
                                             512, y1rawB, nullptr,
                                             512, 1024, 512, nullptr, nullptr);
    cudaEventRecord(ev4, s1);
    k_gus_blur<<<512, 256>>>(ralout, gxn, gusb);
    gemm3_ab<<<dim3(16, 8, 1), 256>>>(down_w, 1024, gusb, gusb, 512, y1raw,
                                      nullptr, 512, 1024, 512, nullptr, nullptr);
    cudaStreamWaitEvent(0, ev4, 0);
    k_add_inorm_lrelu<<<512, 256>>>(y1raw, y1rawB, y1);

    // fuse-final: y2raw += fuse_w[:,:512] * y1
    cudaStreamWaitEvent(0, ev5, 0);
    gemm3_ab<<<dim3(16, 8, 1), 256>>>(fuse_w, 1024, y1, y1, 512, y2raw,
                                      y2raw, 512, 1024, 512, nullptr, nullptr);
    k_inorm_lrelu<<<512, 256>>>(y2raw, out);
}